// round 3
// baseline (speedup 1.0000x reference)
#include <cuda_runtime.h>

// Problem dims (fixed by the dataset)
#define BB 32
#define LL 512
#define DD 1024
#define RR 128
#define M_TOTAL (BB * LL)   // 16384 projected rows

// Scratch: projected tensor T (B*L, R) and squared row norms (B*L)
__device__ __align__(16) float g_t[M_TOTAL * RR];   // 8.4 MB
__device__ float g_sqn[M_TOTAL];

// ---------------------------------------------------------------------------
// Kernel A: T = batch @ proj  (M=16384, K=1024, N=128), fused row sq-norms.
// Block: 256 threads, tile BM=32 rows x BN=128 (full R), BK=32.
// Thread (ty=tid>>5, tx=tid&31) computes a 4x4 microtile:
//   rows ty*4..+3, cols tx*4..+3  (8 ty values x 32 tx values = 32x128)
// Shared layouts are [k][m]-major so the inner loop reads are
// broadcast (A) + canonical float4 (B): conflict-free.
// ---------------------------------------------------------------------------
__global__ __launch_bounds__(256) void proj_norm_kernel(
    const float* __restrict__ batch, const float* __restrict__ proj)
{
    __shared__ __align__(16) float sA[32][33];   // [k][row], pad 1 for STS
    __shared__ __align__(16) float sB[32][128];  // [k][r]

    const int tid = threadIdx.x;
    const int tx = tid & 31;
    const int ty = tid >> 5;
    const int row0 = blockIdx.x * 32;

    float acc[4][4];
#pragma unroll
    for (int i = 0; i < 4; i++)
#pragma unroll
        for (int j = 0; j < 4; j++) acc[i][j] = 0.0f;

    const int a_k4 = tid & 7;    // float4 index along K
    const int a_row = tid >> 3;  // 0..31
    const int b_r4 = tid & 31;   // float4 index along R
    const int b_k = tid >> 5;    // 0..7 (stride 8)

    for (int k0 = 0; k0 < DD; k0 += 32) {
        // Load A tile (32 rows x 32 k), transpose into [k][row]
        {
            float4 v = *reinterpret_cast<const float4*>(
                batch + (size_t)(row0 + a_row) * DD + k0 + a_k4 * 4);
            sA[a_k4 * 4 + 0][a_row] = v.x;
            sA[a_k4 * 4 + 1][a_row] = v.y;
            sA[a_k4 * 4 + 2][a_row] = v.z;
            sA[a_k4 * 4 + 3][a_row] = v.w;
        }
        // Load B tile (32 k x 128 r), natural [k][r]
#pragma unroll
        for (int i = 0; i < 4; i++) {
            int k = b_k + i * 8;
            *reinterpret_cast<float4*>(&sB[k][b_r4 * 4]) =
                *reinterpret_cast<const float4*>(proj + (size_t)(k0 + k) * RR + b_r4 * 4);
        }
        __syncthreads();

#pragma unroll
        for (int k = 0; k < 32; k++) {
            const float a0 = sA[k][ty * 4 + 0];
            const float a1 = sA[k][ty * 4 + 1];
            const float a2 = sA[k][ty * 4 + 2];
            const float a3 = sA[k][ty * 4 + 3];
            const float4 b4 = *reinterpret_cast<const float4*>(&sB[k][tx * 4]);
            acc[0][0] = fmaf(a0, b4.x, acc[0][0]);
            acc[0][1] = fmaf(a0, b4.y, acc[0][1]);
            acc[0][2] = fmaf(a0, b4.z, acc[0][2]);
            acc[0][3] = fmaf(a0, b4.w, acc[0][3]);
            acc[1][0] = fmaf(a1, b4.x, acc[1][0]);
            acc[1][1] = fmaf(a1, b4.y, acc[1][1]);
            acc[1][2] = fmaf(a1, b4.z, acc[1][2]);
            acc[1][3] = fmaf(a1, b4.w, acc[1][3]);
            acc[2][0] = fmaf(a2, b4.x, acc[2][0]);
            acc[2][1] = fmaf(a2, b4.y, acc[2][1]);
            acc[2][2] = fmaf(a2, b4.z, acc[2][2]);
            acc[2][3] = fmaf(a2, b4.w, acc[2][3]);
            acc[3][0] = fmaf(a3, b4.x, acc[3][0]);
            acc[3][1] = fmaf(a3, b4.y, acc[3][1]);
            acc[3][2] = fmaf(a3, b4.z, acc[3][2]);
            acc[3][3] = fmaf(a3, b4.w, acc[3][3]);
        }
        __syncthreads();
    }

    // Store T rows (float4, coalesced) + warp-reduced squared norms.
    // Each warp (fixed ty) owns rows ty*4..ty*4+3 across all 128 cols.
#pragma unroll
    for (int i = 0; i < 4; i++) {
        const int row = row0 + ty * 4 + i;
        float4 v = make_float4(acc[i][0], acc[i][1], acc[i][2], acc[i][3]);
        *reinterpret_cast<float4*>(&g_t[(size_t)row * RR + tx * 4]) = v;
        float s = v.x * v.x + v.y * v.y + v.z * v.z + v.w * v.w;
#pragma unroll
        for (int o = 16; o > 0; o >>= 1) s += __shfl_xor_sync(0xffffffffu, s, o);
        if (tx == 0) g_sqn[row] = s;
    }
}

// ---------------------------------------------------------------------------
// Kernel B: per-batch pairwise distances.
// D[b,i,j] = max(n_i + n_j - 2 * <t_i, t_j>, 0)
// Tile 64x64 per block, K=128 in BK=32 chunks. 256 threads, 4x4 microtile:
//   trow = tid>>4 (0..15) -> rows trow*4..+3 ; tcol = tid&15 -> cols tcol*4..+3
// Shared [k][m] layout (stride 68, 16B-aligned reads): A-read is a 2-address
// broadcast, B-read is the canonical float4 pattern.
// ---------------------------------------------------------------------------
__global__ __launch_bounds__(256) void pdist_kernel(float* __restrict__ out)
{
    __shared__ __align__(16) float sA[32][68];  // [k][i-row]
    __shared__ __align__(16) float sB[32][68];  // [k][j-row]

    const int tid = threadIdx.x;
    const int tcol = tid & 15;
    const int trow = tid >> 4;
    const int b = blockIdx.z;
    const int i0 = blockIdx.y * 64;
    const int j0 = blockIdx.x * 64;
    const float* tbase = g_t + (size_t)b * LL * RR;

    float acc[4][4];
#pragma unroll
    for (int i = 0; i < 4; i++)
#pragma unroll
        for (int j = 0; j < 4; j++) acc[i][j] = 0.0f;

    const int l_k4 = tid & 7;    // float4 index along K chunk
    const int l_row = tid >> 3;  // 0..31, second half at +32

    for (int k0 = 0; k0 < RR; k0 += 32) {
#pragma unroll
        for (int h = 0; h < 2; h++) {
            const int row = l_row + h * 32;
            float4 va = *reinterpret_cast<const float4*>(
                tbase + (size_t)(i0 + row) * RR + k0 + l_k4 * 4);
            sA[l_k4 * 4 + 0][row] = va.x;
            sA[l_k4 * 4 + 1][row] = va.y;
            sA[l_k4 * 4 + 2][row] = va.z;
            sA[l_k4 * 4 + 3][row] = va.w;
            float4 vb = *reinterpret_cast<const float4*>(
                tbase + (size_t)(j0 + row) * RR + k0 + l_k4 * 4);
            sB[l_k4 * 4 + 0][row] = vb.x;
            sB[l_k4 * 4 + 1][row] = vb.y;
            sB[l_k4 * 4 + 2][row] = vb.z;
            sB[l_k4 * 4 + 3][row] = vb.w;
        }
        __syncthreads();

#pragma unroll
        for (int k = 0; k < 32; k++) {
            const float4 a = *reinterpret_cast<const float4*>(&sA[k][trow * 4]);
            const float4 c = *reinterpret_cast<const float4*>(&sB[k][tcol * 4]);
            acc[0][0] = fmaf(a.x, c.x, acc[0][0]);
            acc[0][1] = fmaf(a.x, c.y, acc[0][1]);
            acc[0][2] = fmaf(a.x, c.z, acc[0][2]);
            acc[0][3] = fmaf(a.x, c.w, acc[0][3]);
            acc[1][0] = fmaf(a.y, c.x, acc[1][0]);
            acc[1][1] = fmaf(a.y, c.y, acc[1][1]);
            acc[1][2] = fmaf(a.y, c.z, acc[1][2]);
            acc[1][3] = fmaf(a.y, c.w, acc[1][3]);
            acc[2][0] = fmaf(a.z, c.x, acc[2][0]);
            acc[2][1] = fmaf(a.z, c.y, acc[2][1]);
            acc[2][2] = fmaf(a.z, c.z, acc[2][2]);
            acc[2][3] = fmaf(a.z, c.w, acc[2][3]);
            acc[3][0] = fmaf(a.w, c.x, acc[3][0]);
            acc[3][1] = fmaf(a.w, c.y, acc[3][1]);
            acc[3][2] = fmaf(a.w, c.z, acc[3][2]);
            acc[3][3] = fmaf(a.w, c.w, acc[3][3]);
        }
        __syncthreads();
    }

    // Epilogue: d = n_i + n_j - 2*dot, clamp at 0, float4 coalesced stores.
    float ni[4], nj[4];
#pragma unroll
    for (int i = 0; i < 4; i++) ni[i] = g_sqn[(size_t)b * LL + i0 + trow * 4 + i];
#pragma unroll
    for (int j = 0; j < 4; j++) nj[j] = g_sqn[(size_t)b * LL + j0 + tcol * 4 + j];

#pragma unroll
    for (int i = 0; i < 4; i++) {
        float4 v;
        v.x = fmaxf(ni[i] + nj[0] - 2.0f * acc[i][0], 0.0f);
        v.y = fmaxf(ni[i] + nj[1] - 2.0f * acc[i][1], 0.0f);
        v.z = fmaxf(ni[i] + nj[2] - 2.0f * acc[i][2], 0.0f);
        v.w = fmaxf(ni[i] + nj[3] - 2.0f * acc[i][3], 0.0f);
        const size_t o = ((size_t)b * LL + i0 + trow * 4 + i) * LL + j0 + tcol * 4;
        *reinterpret_cast<float4*>(out + o) = v;
    }
}

extern "C" void kernel_launch(void* const* d_in, const int* in_sizes, int n_in,
                              void* d_out, int out_size)
{
    const float* batch = (const float*)d_in[0];  // (32, 512, 1024) f32
    const float* proj  = (const float*)d_in[1];  // (1024, 128) f32
    float* out = (float*)d_out;                  // (32, 512, 512) f32

    proj_norm_kernel<<<M_TOTAL / 32, 256>>>(batch, proj);
    dim3 grid(LL / 64, LL / 64, BB);
    pdist_kernel<<<grid, 256>>>(out);
}

// round 7
// speedup vs baseline: 2.2947x; 2.2947x over previous
#include <cuda_runtime.h>
#include <cuda_bf16.h>
#include <cstdint>

#define BB 32
#define LL 512
#define DD 1024
#define RR 128
#define M_TOTAL (BB * LL)   // 16384

// ---------------- global scratch ----------------
__device__ __align__(16) __nv_bfloat16 g_pT_hi[RR * DD];     // projT hi [128][1024]
__device__ __align__(16) __nv_bfloat16 g_pT_lo[RR * DD];     // projT lo
__device__ __align__(16) __nv_bfloat16 g_thi[M_TOTAL * RR];  // T hi [16384][128]
__device__ __align__(16) __nv_bfloat16 g_tlo[M_TOTAL * RR];  // T lo
__device__ float g_sqn[M_TOTAL];

// ---------------- helpers (arch-feature-free PTX only) ----------------
__device__ __forceinline__ uint32_t smem_u32(const void* p) {
    uint32_t a;
    asm("{ .reg .u64 t; cvta.to.shared.u64 t, %1; cvt.u32.u64 %0, t; }" : "=r"(a) : "l"(p));
    return a;
}
__device__ __forceinline__ void ldsm4(uint32_t r[4], uint32_t addr) {
    asm volatile("ldmatrix.sync.aligned.m8n8.x4.shared.b16 {%0,%1,%2,%3}, [%4];"
                 : "=r"(r[0]), "=r"(r[1]), "=r"(r[2]), "=r"(r[3]) : "r"(addr));
}
__device__ __forceinline__ void mma_bf16(float d[4], const uint32_t a[4],
                                         uint32_t b0, uint32_t b1) {
    asm volatile(
        "mma.sync.aligned.m16n8k16.row.col.f32.bf16.bf16.f32 "
        "{%0,%1,%2,%3},{%4,%5,%6,%7},{%8,%9},{%0,%1,%2,%3};"
        : "+f"(d[0]), "+f"(d[1]), "+f"(d[2]), "+f"(d[3])
        : "r"(a[0]), "r"(a[1]), "r"(a[2]), "r"(a[3]), "r"(b0), "r"(b1));
}
// hi = top-16-bit truncation (exact bf16); packers
__device__ __forceinline__ uint32_t pack_hi(uint32_t fa, uint32_t fb) {
    return __byte_perm(fa, fb, 0x7632);
}
__device__ __forceinline__ uint32_t pack_bf16x2(float a, float b) {
    uint32_t r;
    asm("cvt.rn.bf16x2.f32 %0, %1, %2;" : "=r"(r) : "f"(b), "f"(a));  // lo=a, hi=b
    return r;
}

// ---------------------------------------------------------------------------
// Kernel 0: split proj (D,R) fp32 -> projT hi/lo (R,D) bf16, K-major
// ---------------------------------------------------------------------------
__global__ void prep_proj_kernel(const float* __restrict__ proj) {
    int k = blockIdx.x;   // 0..1023
    int r = threadIdx.x;  // 0..127
    float f = proj[k * RR + r];
    float fh = __uint_as_float(__float_as_uint(f) & 0xffff0000u);
    g_pT_hi[r * DD + k] = __float2bfloat16(fh);
    g_pT_lo[r * DD + k] = __float2bfloat16(f - fh);
}

// ---------------------------------------------------------------------------
// Kernel 1: T = batch @ proj  (M=16384, K=1024, N=128) via mma.sync bf16 hi/lo.
// 256 thr (8 warps), CTA tile 128x128, BK=32, warp tile 16x128.
// smem rows padded to 80B (40 bf16) -> conflict-free ldmatrix/STS.
// Register-prefetch software pipeline hides gmem latency.
// ---------------------------------------------------------------------------
#define S1 40  // bf16 stride (80B)

__global__ __launch_bounds__(256) void gemm1_kernel(const float* __restrict__ batch) {
    __shared__ __align__(16) __nv_bfloat16 sAh[128 * S1];
    __shared__ __align__(16) __nv_bfloat16 sAl[128 * S1];
    __shared__ __align__(16) __nv_bfloat16 sBh[128 * S1];
    __shared__ __align__(16) __nv_bfloat16 sBl[128 * S1];

    const int tid = threadIdx.x;
    const int wid = tid >> 5;
    const int lane = tid & 31;
    const int row0 = blockIdx.x * 128;

    const uint32_t ah = smem_u32(sAh), al = smem_u32(sAl);
    const uint32_t bh = smem_u32(sBh), bl = smem_u32(sBl);

    // load mappings
    const int a_row = tid >> 3, a_k4 = tid & 7;     // + 32-row steps (4 chunks)
    const int b_row = tid >> 2, b_kc = tid & 3;     // + 64-row steps (2 chunks)

    // ldmatrix lane addresses
    const uint32_t a_off = (uint32_t)((wid * 16 + (lane & 15)) * 80 + ((lane >> 4) & 1) * 16);
    const uint32_t b_off = (uint32_t)(((lane & 7) + ((lane >> 4) & 1) * 8) * 80 + ((lane >> 3) & 1) * 16);

    float acc[16][4];
#pragma unroll
    for (int i = 0; i < 16; i++)
#pragma unroll
        for (int j = 0; j < 4; j++) acc[i][j] = 0.0f;

    float4 pfa[4];
    uint4 pfbh[2], pfbl[2];
    // prefetch iter 0
#pragma unroll
    for (int i = 0; i < 4; i++)
        pfa[i] = *reinterpret_cast<const float4*>(
            batch + (size_t)(row0 + a_row + i * 32) * DD + a_k4 * 4);
#pragma unroll
    for (int i = 0; i < 2; i++) {
        pfbh[i] = *reinterpret_cast<const uint4*>(g_pT_hi + (size_t)(b_row + i * 64) * DD + b_kc * 8);
        pfbl[i] = *reinterpret_cast<const uint4*>(g_pT_lo + (size_t)(b_row + i * 64) * DD + b_kc * 8);
    }

    for (int it = 0; it < 32; ++it) {
        // STS phase: convert A to hi/lo, copy B
#pragma unroll
        for (int i = 0; i < 4; i++) {
            float4 v = pfa[i];
            uint32_t ux = __float_as_uint(v.x), uy = __float_as_uint(v.y);
            uint32_t uz = __float_as_uint(v.z), uw = __float_as_uint(v.w);
            uint32_t h01 = pack_hi(ux, uy), h23 = pack_hi(uz, uw);
            float lx = v.x - __uint_as_float(ux & 0xffff0000u);
            float ly = v.y - __uint_as_float(uy & 0xffff0000u);
            float lz = v.z - __uint_as_float(uz & 0xffff0000u);
            float lw = v.w - __uint_as_float(uw & 0xffff0000u);
            uint32_t l01 = pack_bf16x2(lx, ly), l23 = pack_bf16x2(lz, lw);
            const uint32_t off = (uint32_t)((a_row + i * 32) * 80 + a_k4 * 8);
            asm volatile("st.shared.v2.b32 [%0], {%1,%2};" :: "r"(ah + off), "r"(h01), "r"(h23) : "memory");
            asm volatile("st.shared.v2.b32 [%0], {%1,%2};" :: "r"(al + off), "r"(l01), "r"(l23) : "memory");
        }
#pragma unroll
        for (int i = 0; i < 2; i++) {
            const uint32_t off = (uint32_t)((b_row + i * 64) * 80 + b_kc * 16);
            asm volatile("st.shared.v4.b32 [%0], {%1,%2,%3,%4};"
                :: "r"(bh + off), "r"(pfbh[i].x), "r"(pfbh[i].y), "r"(pfbh[i].z), "r"(pfbh[i].w) : "memory");
            asm volatile("st.shared.v4.b32 [%0], {%1,%2,%3,%4};"
                :: "r"(bl + off), "r"(pfbl[i].x), "r"(pfbl[i].y), "r"(pfbl[i].z), "r"(pfbl[i].w) : "memory");
        }
        __syncthreads();

        // prefetch next K-tile (gmem latency overlaps compute below)
        if (it < 31) {
            const int k0n = (it + 1) * 32;
#pragma unroll
            for (int i = 0; i < 4; i++)
                pfa[i] = *reinterpret_cast<const float4*>(
                    batch + (size_t)(row0 + a_row + i * 32) * DD + k0n + a_k4 * 4);
#pragma unroll
            for (int i = 0; i < 2; i++) {
                pfbh[i] = *reinterpret_cast<const uint4*>(g_pT_hi + (size_t)(b_row + i * 64) * DD + k0n + b_kc * 8);
                pfbl[i] = *reinterpret_cast<const uint4*>(g_pT_lo + (size_t)(b_row + i * 64) * DD + k0n + b_kc * 8);
            }
        }

        // compute: 2 k16 steps
#pragma unroll
        for (int s = 0; s < 2; ++s) {
            uint32_t Ah[4], Al4[4];
            ldsm4(Ah, ah + a_off + s * 32);
            ldsm4(Al4, al + a_off + s * 32);
#pragma unroll
            for (int nt = 0; nt < 8; ++nt) {
                uint32_t Bh4[4], Bl4[4];
                ldsm4(Bh4, bh + b_off + nt * (16 * 80) + s * 32);
                ldsm4(Bl4, bl + b_off + nt * (16 * 80) + s * 32);
                mma_bf16(acc[nt * 2 + 0], Ah, Bh4[0], Bh4[1]);
                mma_bf16(acc[nt * 2 + 1], Ah, Bh4[2], Bh4[3]);
                mma_bf16(acc[nt * 2 + 0], Ah, Bl4[0], Bl4[1]);
                mma_bf16(acc[nt * 2 + 1], Ah, Bl4[2], Bl4[3]);
                mma_bf16(acc[nt * 2 + 0], Al4, Bh4[0], Bh4[1]);
                mma_bf16(acc[nt * 2 + 1], Al4, Bh4[2], Bh4[3]);
            }
        }
        __syncthreads();
    }

    // Epilogue: rows r0 = wid*16 + (lane>>2), r1 = r0+8 (warp-private rows).
    const int r0g = row0 + wid * 16 + (lane >> 2);
    const int r1g = r0g + 8;
    uint32_t* thi32 = reinterpret_cast<uint32_t*>(g_thi);
    uint32_t* tlo32 = reinterpret_cast<uint32_t*>(g_tlo);
    float sq0 = 0.0f, sq1 = 0.0f;
#pragma unroll
    for (int nt = 0; nt < 16; ++nt) {
        const int cidx = nt * 4 + (lane & 3);  // uint32 (2-col) index within 64
        float f0 = acc[nt][0], f1 = acc[nt][1], f2 = acc[nt][2], f3 = acc[nt][3];
        sq0 = fmaf(f0, f0, sq0); sq0 = fmaf(f1, f1, sq0);
        sq1 = fmaf(f2, f2, sq1); sq1 = fmaf(f3, f3, sq1);
        uint32_t u0 = __float_as_uint(f0), u1 = __float_as_uint(f1);
        uint32_t u2 = __float_as_uint(f2), u3 = __float_as_uint(f3);
        thi32[(size_t)r0g * 64 + cidx] = pack_hi(u0, u1);
        thi32[(size_t)r1g * 64 + cidx] = pack_hi(u2, u3);
        tlo32[(size_t)r0g * 64 + cidx] = pack_bf16x2(
            f0 - __uint_as_float(u0 & 0xffff0000u), f1 - __uint_as_float(u1 & 0xffff0000u));
        tlo32[(size_t)r1g * 64 + cidx] = pack_bf16x2(
            f2 - __uint_as_float(u2 & 0xffff0000u), f3 - __uint_as_float(u3 & 0xffff0000u));
    }
#pragma unroll
    for (int o = 1; o <= 2; o <<= 1) {
        sq0 += __shfl_xor_sync(0xffffffffu, sq0, o);
        sq1 += __shfl_xor_sync(0xffffffffu, sq1, o);
    }
    if ((lane & 3) == 0) { g_sqn[r0g] = sq0; g_sqn[r1g] = sq1; }
}

// ---------------------------------------------------------------------------
// Kernel 2: per-batch Gram 128x128 tile + distance epilogue, K=128 one-shot.
// smem rows padded to 272B (136 bf16). 4 tiles (Ah,Al,Bh,Bl) = 136KB dynamic.
// ---------------------------------------------------------------------------
#define S2B 272                       // bytes per smem row
#define G2_TILE (128 * S2B)           // 34816
#define G2_SMEM (4 * G2_TILE + 1024)  // + sNi/sNj

__global__ __launch_bounds__(256) void gemm2_kernel(float* __restrict__ out) {
    extern __shared__ __align__(16) char smem[];
    const uint32_t ah = smem_u32(smem);
    const uint32_t al = ah + G2_TILE;
    const uint32_t bh = ah + 2 * G2_TILE;
    const uint32_t bl = ah + 3 * G2_TILE;
    float* sNi = reinterpret_cast<float*>(smem + 4 * G2_TILE);
    float* sNj = sNi + 128;

    const int tid = threadIdx.x;
    const int wid = tid >> 5;
    const int lane = tid & 31;
    const int b = blockIdx.x >> 4;
    const int tix = blockIdx.x & 15;
    const int i0 = (tix >> 2) * 128;
    const int j0 = (tix & 3) * 128;

    if (tid < 128) sNi[tid] = g_sqn[b * LL + i0 + tid];
    else sNj[tid - 128] = g_sqn[b * LL + j0 + (tid - 128)];

    // Load 4 tiles: [128 rows][128 k] bf16 each, 8 uint4/thread.
    const __nv_bfloat16* srcs[4] = {
        g_thi + (size_t)(b * LL + i0) * RR, g_tlo + (size_t)(b * LL + i0) * RR,
        g_thi + (size_t)(b * LL + j0) * RR, g_tlo + (size_t)(b * LL + j0) * RR };
    const uint32_t dsts[4] = { ah, al, bh, bl };
#pragma unroll
    for (int r = 0; r < 4; ++r) {
        const __nv_bfloat16* src = srcs[r];
        const uint32_t dst = dsts[r];
#pragma unroll
        for (int t = 0; t < 8; ++t) {
            const int c = tid + t * 256;       // 0..2047
            const int row = c >> 4, kc = c & 15;
            uint4 v = *reinterpret_cast<const uint4*>(src + (size_t)row * RR + kc * 8);
            asm volatile("st.shared.v4.b32 [%0], {%1,%2,%3,%4};"
                :: "r"(dst + row * S2B + kc * 16), "r"(v.x), "r"(v.y), "r"(v.z), "r"(v.w) : "memory");
        }
    }
    __syncthreads();

    const uint32_t a_off = (uint32_t)((wid * 16 + (lane & 15)) * S2B + ((lane >> 4) & 1) * 16);
    const uint32_t b_off = (uint32_t)(((lane & 7) + ((lane >> 4) & 1) * 8) * S2B + ((lane >> 3) & 1) * 16);

    float acc[16][4];
#pragma unroll
    for (int i = 0; i < 16; i++)
#pragma unroll
        for (int j = 0; j < 4; j++) acc[i][j] = 0.0f;

#pragma unroll
    for (int s = 0; s < 8; ++s) {
        uint32_t Ah[4], Al4[4];
        ldsm4(Ah, ah + a_off + s * 32);
        ldsm4(Al4, al + a_off + s * 32);
#pragma unroll
        for (int nt = 0; nt < 8; ++nt) {
            uint32_t Bh4[4], Bl4[4];
            ldsm4(Bh4, bh + b_off + nt * (16 * S2B) + s * 32);
            ldsm4(Bl4, bl + b_off + nt * (16 * S2B) + s * 32);
            mma_bf16(acc[nt * 2 + 0], Ah, Bh4[0], Bh4[1]);
            mma_bf16(acc[nt * 2 + 1], Ah, Bh4[2], Bh4[3]);
            mma_bf16(acc[nt * 2 + 0], Ah, Bl4[0], Bl4[1]);
            mma_bf16(acc[nt * 2 + 1], Ah, Bl4[2], Bl4[3]);
            mma_bf16(acc[nt * 2 + 0], Al4, Bh4[0], Bh4[1]);
            mma_bf16(acc[nt * 2 + 1], Al4, Bh4[2], Bh4[3]);
        }
    }

    // Epilogue: d = max(ni + nj - 2c, 0); float2 stores.
    const int r0l = wid * 16 + (lane >> 2);
    const float ni0 = sNi[r0l], ni1 = sNi[r0l + 8];
    float* o0 = out + ((size_t)(b * LL + i0 + r0l)) * LL + j0;
    float* o1 = o0 + 8 * LL;
#pragma unroll
    for (int nt = 0; nt < 16; ++nt) {
        const int col = nt * 8 + (lane & 3) * 2;
        const float nj0 = sNj[col], nj1 = sNj[col + 1];
        float2 v0, v1;
        v0.x = fmaxf(ni0 + nj0 - 2.0f * acc[nt][0], 0.0f);
        v0.y = fmaxf(ni0 + nj1 - 2.0f * acc[nt][1], 0.0f);
        v1.x = fmaxf(ni1 + nj0 - 2.0f * acc[nt][2], 0.0f);
        v1.y = fmaxf(ni1 + nj1 - 2.0f * acc[nt][3], 0.0f);
        *reinterpret_cast<float2*>(o0 + col) = v0;
        *reinterpret_cast<float2*>(o1 + col) = v1;
    }
}

extern "C" void kernel_launch(void* const* d_in, const int* in_sizes, int n_in,
                              void* d_out, int out_size)
{
    const float* batch = (const float*)d_in[0];  // (32, 512, 1024) f32
    const float* proj  = (const float*)d_in[1];  // (1024, 128) f32
    float* out = (float*)d_out;                  // (32, 512, 512) f32

    cudaFuncSetAttribute(gemm2_kernel, cudaFuncAttributeMaxDynamicSharedMemorySize, G2_SMEM);

    prep_proj_kernel<<<DD, RR>>>(proj);
    gemm1_kernel<<<M_TOTAL / 128, 256>>>(batch);
    gemm2_kernel<<<BB * 16, 256, G2_SMEM>>>(out);
}

// round 10
// speedup vs baseline: 2.7294x; 1.1895x over previous
#include <cuda_runtime.h>
#include <cuda_bf16.h>
#include <cstdint>

#define BB 32
#define LL 512
#define DD 1024
#define RR 128
#define M_TOTAL (BB * LL)   // 16384

// ---------------- global scratch ----------------
__device__ __align__(16) __nv_bfloat16 g_pT_hi[RR * DD];     // projT hi [128][1024]
__device__ __align__(16) __nv_bfloat16 g_pT_lo[RR * DD];     // projT lo
__device__ __align__(16) __nv_bfloat16 g_thi[M_TOTAL * RR];  // T hi [16384][128]
__device__ __align__(16) __nv_bfloat16 g_tlo[M_TOTAL * RR];  // T lo
__device__ float g_sqn[M_TOTAL];

__constant__ int c_ti[10] = {0,0,0,0,1,1,1,2,2,3};
__constant__ int c_tj[10] = {0,1,2,3,1,2,3,2,3,3};

// ---------------- helpers (arch-feature-free PTX only) ----------------
__device__ __forceinline__ uint32_t smem_u32(const void* p) {
    uint32_t a;
    asm("{ .reg .u64 t; cvta.to.shared.u64 t, %1; cvt.u32.u64 %0, t; }" : "=r"(a) : "l"(p));
    return a;
}
__device__ __forceinline__ void ldsm4(uint32_t r[4], uint32_t addr) {
    asm volatile("ldmatrix.sync.aligned.m8n8.x4.shared.b16 {%0,%1,%2,%3}, [%4];"
                 : "=r"(r[0]), "=r"(r[1]), "=r"(r[2]), "=r"(r[3]) : "r"(addr));
}
__device__ __forceinline__ void mma_bf16(float d[4], const uint32_t a[4],
                                         uint32_t b0, uint32_t b1) {
    asm volatile(
        "mma.sync.aligned.m16n8k16.row.col.f32.bf16.bf16.f32 "
        "{%0,%1,%2,%3},{%4,%5,%6,%7},{%8,%9},{%0,%1,%2,%3};"
        : "+f"(d[0]), "+f"(d[1]), "+f"(d[2]), "+f"(d[3])
        : "r"(a[0]), "r"(a[1]), "r"(a[2]), "r"(a[3]), "r"(b0), "r"(b1));
}
#define CP16(dst, src) \
    asm volatile("cp.async.cg.shared.global [%0], [%1], 16;" :: "r"(dst), "l"(src) : "memory")
#define CP_COMMIT() asm volatile("cp.async.commit_group;" ::: "memory")
#define CP_WAIT(n)  asm volatile("cp.async.wait_group %0;" :: "n"(n) : "memory")

__device__ __forceinline__ uint32_t pack_hi(uint32_t fa, uint32_t fb) {
    return __byte_perm(fa, fb, 0x7632);
}
__device__ __forceinline__ uint32_t pack_bf16x2(float a, float b) {
    uint32_t r;
    asm("cvt.rn.bf16x2.f32 %0, %1, %2;" : "=r"(r) : "f"(b), "f"(a));  // lo=a, hi=b
    return r;
}

// ---------------------------------------------------------------------------
// Kernel 0: split proj (D,R) fp32 -> projT hi/lo (R,D) bf16, coalesced via
// smem tile transpose. Grid (16 k-tiles, 2 r-tiles), 256 thr, 64x64 tiles.
// ---------------------------------------------------------------------------
__global__ __launch_bounds__(256) void prep_proj_kernel(const float* __restrict__ proj) {
    __shared__ float sT[64][65];
    const int tid = threadIdx.x;
    const int k0 = blockIdx.x * 64;
    const int r0 = blockIdx.y * 64;

#pragma unroll
    for (int t = 0; t < 8; ++t) {
        const int idx = tid + t * 256;           // 2048 float2 chunks
        const int k = idx >> 5, c2 = idx & 31;
        float2 v = *reinterpret_cast<const float2*>(proj + (size_t)(k0 + k) * RR + r0 + c2 * 2);
        sT[k][c2 * 2] = v.x;
        sT[k][c2 * 2 + 1] = v.y;
    }
    __syncthreads();

#pragma unroll
    for (int t = 0; t < 4; ++t) {
        const int idx = tid + t * 256;           // 1024 4-elem chunks
        const int r = idx >> 4, kq = idx & 15;
        float f[4], fh[4];
        uint32_t u[4];
#pragma unroll
        for (int e = 0; e < 4; ++e) {
            f[e] = sT[kq * 4 + e][r];
            u[e] = __float_as_uint(f[e]);
            fh[e] = __uint_as_float(u[e] & 0xffff0000u);
        }
        uint2 hv = make_uint2(pack_hi(u[0], u[1]), pack_hi(u[2], u[3]));
        uint2 lv = make_uint2(pack_bf16x2(f[0] - fh[0], f[1] - fh[1]),
                              pack_bf16x2(f[2] - fh[2], f[3] - fh[3]));
        const size_t o = (size_t)(r0 + r) * DD + k0 + kq * 4;
        *reinterpret_cast<uint2*>(g_pT_hi + o) = hv;
        *reinterpret_cast<uint2*>(g_pT_lo + o) = lv;
    }
}

// ---------------------------------------------------------------------------
// Kernel 1: T = batch @ proj (16384x128, K=1024), mma.sync bf16 hi/lo.
// 256 thr, CTA tile 128x128, BK=32, warp tile 16x128.
// Double-buffered dynamic smem (2 x 40KB); B via cp.async, A via reg pipeline.
// ---------------------------------------------------------------------------
#define S1B 80                 // bytes per smem row
#define G1_ARR (128 * S1B)     // 10240
#define G1_BUF (4 * G1_ARR)    // 40960
#define G1_SMEM (2 * G1_BUF)   // 81920

__global__ __launch_bounds__(256) void gemm1_kernel(const float* __restrict__ batch) {
    extern __shared__ __align__(16) char sm1[];
    const uint32_t base = smem_u32(sm1);

    const int tid = threadIdx.x;
    const int wid = tid >> 5;
    const int lane = tid & 31;
    const int row0 = blockIdx.x * 128;

    const int a_row = tid >> 3, a_k4 = tid & 7;   // A: 128 rows x 8 float4

    const uint32_t a_off = (uint32_t)((wid * 16 + (lane & 15)) * S1B + ((lane >> 4) & 1) * 16);
    const uint32_t b_off = (uint32_t)(((lane & 7) + ((lane >> 4) & 1) * 8) * S1B + ((lane >> 3) & 1) * 16);

    float acc[16][4];
#pragma unroll
    for (int i = 0; i < 16; i++)
#pragma unroll
        for (int j = 0; j < 4; j++) acc[i][j] = 0.0f;

    float4 pfa[4];

    // ---- prologue: iter 0 ----
#pragma unroll
    for (int i = 0; i < 4; i++)
        pfa[i] = *reinterpret_cast<const float4*>(
            batch + (size_t)(row0 + a_row + i * 32) * DD + a_k4 * 4);
    {
        const uint32_t bb = base;
#pragma unroll
        for (int t = 0; t < 2; ++t) {
            const int c = tid + t * 256;       // 512 chunks per tile
            const int row = c >> 2, kc = c & 3;
            const uint32_t off = (uint32_t)(row * S1B + kc * 16);
            CP16(bb + 2 * G1_ARR + off, g_pT_hi + (size_t)row * DD + kc * 8);
            CP16(bb + 3 * G1_ARR + off, g_pT_lo + (size_t)row * DD + kc * 8);
        }
        CP_COMMIT();
        // STS A iter 0
#pragma unroll
        for (int i = 0; i < 4; i++) {
            float4 v = pfa[i];
            uint32_t ux = __float_as_uint(v.x), uy = __float_as_uint(v.y);
            uint32_t uz = __float_as_uint(v.z), uw = __float_as_uint(v.w);
            uint32_t h01 = pack_hi(ux, uy), h23 = pack_hi(uz, uw);
            uint32_t l01 = pack_bf16x2(v.x - __uint_as_float(ux & 0xffff0000u),
                                       v.y - __uint_as_float(uy & 0xffff0000u));
            uint32_t l23 = pack_bf16x2(v.z - __uint_as_float(uz & 0xffff0000u),
                                       v.w - __uint_as_float(uw & 0xffff0000u));
            const uint32_t off = (uint32_t)((a_row + i * 32) * S1B + a_k4 * 8);
            asm volatile("st.shared.v2.b32 [%0], {%1,%2};" :: "r"(bb + off), "r"(h01), "r"(h23) : "memory");
            asm volatile("st.shared.v2.b32 [%0], {%1,%2};" :: "r"(bb + G1_ARR + off), "r"(l01), "r"(l23) : "memory");
        }
    }
    CP_WAIT(0);
    __syncthreads();

    for (int it = 0; it < 32; ++it) {
        const int p = it & 1;
        const int np = p ^ 1;
        const uint32_t bb = base + p * G1_BUF;
        const uint32_t nb = base + np * G1_BUF;

        if (it < 31) {
            const int k0n = (it + 1) * 32;
            // B next tile via cp.async into the other buffer
#pragma unroll
            for (int t = 0; t < 2; ++t) {
                const int c = tid + t * 256;
                const int row = c >> 2, kc = c & 3;
                const uint32_t off = (uint32_t)(row * S1B + kc * 16);
                CP16(nb + 2 * G1_ARR + off, g_pT_hi + (size_t)row * DD + k0n + kc * 8);
                CP16(nb + 3 * G1_ARR + off, g_pT_lo + (size_t)row * DD + k0n + kc * 8);
            }
            CP_COMMIT();
            // A next tile into regs
#pragma unroll
            for (int i = 0; i < 4; i++)
                pfa[i] = *reinterpret_cast<const float4*>(
                    batch + (size_t)(row0 + a_row + i * 32) * DD + k0n + a_k4 * 4);
        }

        // compute on buffer p: 2 k16 steps
#pragma unroll
        for (int s = 0; s < 2; ++s) {
            uint32_t Ah[4], Al4[4];
            ldsm4(Ah, bb + a_off + s * 32);
            ldsm4(Al4, bb + G1_ARR + a_off + s * 32);
#pragma unroll
            for (int nt = 0; nt < 8; ++nt) {
                uint32_t Bh4[4], Bl4[4];
                ldsm4(Bh4, bb + 2 * G1_ARR + b_off + nt * (16 * S1B) + s * 32);
                ldsm4(Bl4, bb + 3 * G1_ARR + b_off + nt * (16 * S1B) + s * 32);
                mma_bf16(acc[nt * 2 + 0], Ah, Bh4[0], Bh4[1]);
                mma_bf16(acc[nt * 2 + 1], Ah, Bh4[2], Bh4[3]);
                mma_bf16(acc[nt * 2 + 0], Ah, Bl4[0], Bl4[1]);
                mma_bf16(acc[nt * 2 + 1], Ah, Bl4[2], Bl4[3]);
                mma_bf16(acc[nt * 2 + 0], Al4, Bh4[0], Bh4[1]);
                mma_bf16(acc[nt * 2 + 1], Al4, Bh4[2], Bh4[3]);
            }
        }

        if (it < 31) {
            // STS A next into other buffer
#pragma unroll
            for (int i = 0; i < 4; i++) {
                float4 v = pfa[i];
                uint32_t ux = __float_as_uint(v.x), uy = __float_as_uint(v.y);
                uint32_t uz = __float_as_uint(v.z), uw = __float_as_uint(v.w);
                uint32_t h01 = pack_hi(ux, uy), h23 = pack_hi(uz, uw);
                uint32_t l01 = pack_bf16x2(v.x - __uint_as_float(ux & 0xffff0000u),
                                           v.y - __uint_as_float(uy & 0xffff0000u));
                uint32_t l23 = pack_bf16x2(v.z - __uint_as_float(uz & 0xffff0000u),
                                           v.w - __uint_as_float(uw & 0xffff0000u));
                const uint32_t off = (uint32_t)((a_row + i * 32) * S1B + a_k4 * 8);
                asm volatile("st.shared.v2.b32 [%0], {%1,%2};" :: "r"(nb + off), "r"(h01), "r"(h23) : "memory");
                asm volatile("st.shared.v2.b32 [%0], {%1,%2};" :: "r"(nb + G1_ARR + off), "r"(l01), "r"(l23) : "memory");
            }
            CP_WAIT(0);
        }
        __syncthreads();
    }

    // Epilogue: warp-private rows r0 = wid*16 + lane>>2, r1 = r0+8.
    const int r0g = row0 + wid * 16 + (lane >> 2);
    const int r1g = r0g + 8;
    uint32_t* thi32 = reinterpret_cast<uint32_t*>(g_thi);
    uint32_t* tlo32 = reinterpret_cast<uint32_t*>(g_tlo);
    float sq0 = 0.0f, sq1 = 0.0f;
#pragma unroll
    for (int nt = 0; nt < 16; ++nt) {
        const int cidx = nt * 4 + (lane & 3);
        float f0 = acc[nt][0], f1 = acc[nt][1], f2 = acc[nt][2], f3 = acc[nt][3];
        sq0 = fmaf(f0, f0, sq0); sq0 = fmaf(f1, f1, sq0);
        sq1 = fmaf(f2, f2, sq1); sq1 = fmaf(f3, f3, sq1);
        uint32_t u0 = __float_as_uint(f0), u1 = __float_as_uint(f1);
        uint32_t u2 = __float_as_uint(f2), u3 = __float_as_uint(f3);
        thi32[(size_t)r0g * 64 + cidx] = pack_hi(u0, u1);
        thi32[(size_t)r1g * 64 + cidx] = pack_hi(u2, u3);
        tlo32[(size_t)r0g * 64 + cidx] = pack_bf16x2(
            f0 - __uint_as_float(u0 & 0xffff0000u), f1 - __uint_as_float(u1 & 0xffff0000u));
        tlo32[(size_t)r1g * 64 + cidx] = pack_bf16x2(
            f2 - __uint_as_float(u2 & 0xffff0000u), f3 - __uint_as_float(u3 & 0xffff0000u));
    }
#pragma unroll
    for (int o = 1; o <= 2; o <<= 1) {
        sq0 += __shfl_xor_sync(0xffffffffu, sq0, o);
        sq1 += __shfl_xor_sync(0xffffffffu, sq1, o);
    }
    if ((lane & 3) == 0) { g_sqn[r0g] = sq0; g_sqn[r1g] = sq1; }
}

// ---------------------------------------------------------------------------
// Kernel 2: symmetric Gram tiles. Grid (10 tile-pairs, 32 batches).
// Upper-triangle 128x128 tiles; off-diagonal writes mirror block via
// conflict-free smem transpose (stride 132 floats). Split-K cp.async loads.
// ---------------------------------------------------------------------------
#define S2B 272                        // bytes per smem row (136 bf16)
#define G2_TILE (128 * S2B)            // 34816
#define G2_SMEM (4 * G2_TILE + 1024)   // + norms

__global__ __launch_bounds__(256) void gemm2_kernel(float* __restrict__ out) {
    extern __shared__ __align__(16) char sm2[];
    const uint32_t ah = smem_u32(sm2);
    const uint32_t al = ah + G2_TILE;
    const uint32_t bh = ah + 2 * G2_TILE;
    const uint32_t bl = ah + 3 * G2_TILE;
    float* sNi = reinterpret_cast<float*>(sm2 + 4 * G2_TILE);
    float* sNj = sNi + 128;
    float* sD  = reinterpret_cast<float*>(sm2);   // transpose staging (aliases A tiles)

    const int tid = threadIdx.x;
    const int wid = tid >> 5;
    const int lane = tid & 31;
    const int b = blockIdx.y;
    const int ti = c_ti[blockIdx.x], tj = c_tj[blockIdx.x];
    const bool diag = (ti == tj);
    const int i0 = ti * 128, j0 = tj * 128;

    const __nv_bfloat16* srcs[4] = {
        g_thi + (size_t)(b * LL + i0) * RR, g_tlo + (size_t)(b * LL + i0) * RR,
        g_thi + (size_t)(b * LL + j0) * RR, g_tlo + (size_t)(b * LL + j0) * RR };
    const uint32_t dsts[4] = { ah, al, bh, bl };
    const int ntile = diag ? 2 : 4;

    // Split-K cp.async: group 0 = k[0,64), group 1 = k[64,128)
#pragma unroll
    for (int h = 0; h < 2; ++h) {
        for (int r = 0; r < ntile; ++r) {
#pragma unroll
            for (int q = 0; q < 4; ++q) {
                const int idx = tid + q * 256;           // 1024 chunks per half-tile
                const int row = idx >> 3, kcl = idx & 7;
                const int kc = h * 8 + kcl;
                CP16(dsts[r] + (uint32_t)(row * S2B + kc * 16),
                     srcs[r] + (size_t)row * RR + kc * 8);
            }
        }
        CP_COMMIT();
    }
    if (tid < 128) sNi[tid] = g_sqn[b * LL + i0 + tid];
    else sNj[tid - 128] = g_sqn[b * LL + j0 + (tid - 128)];

    const uint32_t bhc = diag ? ah : bh;
    const uint32_t blc = diag ? al : bl;
    const uint32_t a_off = (uint32_t)((wid * 16 + (lane & 15)) * S2B + ((lane >> 4) & 1) * 16);
    const uint32_t b_off = (uint32_t)(((lane & 7) + ((lane >> 4) & 1) * 8) * S2B + ((lane >> 3) & 1) * 16);

    float acc[16][4];
#pragma unroll
    for (int i = 0; i < 16; i++)
#pragma unroll
        for (int j = 0; j < 4; j++) acc[i][j] = 0.0f;

    CP_WAIT(1);
    __syncthreads();

#pragma unroll
    for (int s = 0; s < 8; ++s) {
        if (s == 4) { CP_WAIT(0); __syncthreads(); }
        uint32_t Ah[4], Al4[4];
        ldsm4(Ah, ah + a_off + s * 32);
        ldsm4(Al4, al + a_off + s * 32);
#pragma unroll
        for (int nt = 0; nt < 8; ++nt) {
            uint32_t Bh4[4], Bl4[4];
            ldsm4(Bh4, bhc + b_off + nt * (16 * S2B) + s * 32);
            ldsm4(Bl4, blc + b_off + nt * (16 * S2B) + s * 32);
            mma_bf16(acc[nt * 2 + 0], Ah, Bh4[0], Bh4[1]);
            mma_bf16(acc[nt * 2 + 1], Ah, Bh4[2], Bh4[3]);
            mma_bf16(acc[nt * 2 + 0], Ah, Bl4[0], Bl4[1]);
            mma_bf16(acc[nt * 2 + 1], Ah, Bl4[2], Bl4[3]);
            mma_bf16(acc[nt * 2 + 0], Al4, Bh4[0], Bh4[1]);
            mma_bf16(acc[nt * 2 + 1], Al4, Bh4[2], Bh4[3]);
        }
    }
    __syncthreads();   // all ldsm done before sD overwrites tile smem

    // Epilogue: direct store of (i,j) block; stage transposed copy for mirror.
    const int r0l = wid * 16 + (lane >> 2);
    const float ni0 = sNi[r0l], ni1 = sNi[r0l + 8];
    float* o0 = out + ((size_t)(b * LL + i0 + r0l)) * LL + j0;
    float* o1 = o0 + 8 * LL;
#pragma unroll
    for (int nt = 0; nt < 16; ++nt) {
        const int col = nt * 8 + (lane & 3) * 2;
        const float nj0 = sNj[col], nj1 = sNj[col + 1];
        float2 v0, v1;
        v0.x = fmaxf(ni0 + nj0 - 2.0f * acc[nt][0], 0.0f);
        v0.y = fmaxf(ni0 + nj1 - 2.0f * acc[nt][1], 0.0f);
        v1.x = fmaxf(ni1 + nj0 - 2.0f * acc[nt][2], 0.0f);
        v1.y = fmaxf(ni1 + nj1 - 2.0f * acc[nt][3], 0.0f);
        *reinterpret_cast<float2*>(o0 + col) = v0;
        *reinterpret_cast<float2*>(o1 + col) = v1;
        if (!diag) {
            sD[col * 132 + r0l]           = v0.x;   // sD_T[c][r]
            sD[(col + 1) * 132 + r0l]     = v0.y;
            sD[col * 132 + r0l + 8]       = v1.x;
            sD[(col + 1) * 132 + r0l + 8] = v1.y;
        }
    }
    if (!diag) {
        __syncthreads();
#pragma unroll
        for (int t = 0; t < 16; ++t) {
            const int idx = tid + t * 256;
            const int tr = idx >> 5;                 // transposed row = orig col
            float4 v = *reinterpret_cast<const float4*>(sD + (size_t)tr * 132 + lane * 4);
            *reinterpret_cast<float4*>(
                out + ((size_t)(b * LL + j0 + tr)) * LL + i0 + lane * 4) = v;
        }
    }
}

extern "C" void kernel_launch(void* const* d_in, const int* in_sizes, int n_in,
                              void* d_out, int out_size)
{
    const float* batch = (const float*)d_in[0];  // (32, 512, 1024) f32
    const float* proj  = (const float*)d_in[1];  // (1024, 128) f32
    float* out = (float*)d_out;                  // (32, 512, 512) f32

    cudaFuncSetAttribute(gemm1_kernel, cudaFuncAttributeMaxDynamicSharedMemorySize, G1_SMEM);
    cudaFuncSetAttribute(gemm2_kernel, cudaFuncAttributeMaxDynamicSharedMemorySize, G2_SMEM);

    prep_proj_kernel<<<dim3(16, 2), 256>>>(proj);
    gemm1_kernel<<<M_TOTAL / 128, 256, G1_SMEM>>>(batch);
    gemm2_kernel<<<dim3(10, BB), 256, G2_SMEM>>>(out);
}

// round 12
// speedup vs baseline: 2.8940x; 1.0603x over previous
#include <cuda_runtime.h>
#include <cuda_bf16.h>
#include <cstdint>

#define BB 32
#define LL 512
#define DD 1024
#define RR 128
#define M_TOTAL (BB * LL)   // 16384

// ---------------- global scratch ----------------
__device__ __align__(16) __nv_bfloat16 g_pT_hi[RR * DD];     // projT hi [128][1024]
__device__ __align__(16) __nv_bfloat16 g_pT_lo[RR * DD];     // projT lo
__device__ __align__(16) __nv_bfloat16 g_thi[M_TOTAL * RR];  // T hi [16384][128]
__device__ __align__(16) __nv_bfloat16 g_tlo[M_TOTAL * RR];  // T lo
__device__ float g_sqn[M_TOTAL];

__constant__ int c_ti[10] = {0,0,0,0,1,1,1,2,2,3};
__constant__ int c_tj[10] = {0,1,2,3,1,2,3,2,3,3};

// ---------------- helpers (arch-feature-free PTX only) ----------------
__device__ __forceinline__ uint32_t smem_u32(const void* p) {
    uint32_t a;
    asm("{ .reg .u64 t; cvta.to.shared.u64 t, %1; cvt.u32.u64 %0, t; }" : "=r"(a) : "l"(p));
    return a;
}
__device__ __forceinline__ void ldsm4(uint32_t r[4], uint32_t addr) {
    asm volatile("ldmatrix.sync.aligned.m8n8.x4.shared.b16 {%0,%1,%2,%3}, [%4];"
                 : "=r"(r[0]), "=r"(r[1]), "=r"(r[2]), "=r"(r[3]) : "r"(addr));
}
__device__ __forceinline__ void mma_bf16(float d[4], const uint32_t a[4],
                                         uint32_t b0, uint32_t b1) {
    asm volatile(
        "mma.sync.aligned.m16n8k16.row.col.f32.bf16.bf16.f32 "
        "{%0,%1,%2,%3},{%4,%5,%6,%7},{%8,%9},{%0,%1,%2,%3};"
        : "+f"(d[0]), "+f"(d[1]), "+f"(d[2]), "+f"(d[3])
        : "r"(a[0]), "r"(a[1]), "r"(a[2]), "r"(a[3]), "r"(b0), "r"(b1));
}
#define CP16(dst, src) \
    asm volatile("cp.async.cg.shared.global [%0], [%1], 16;" :: "r"(dst), "l"(src) : "memory")
#define CP_COMMIT() asm volatile("cp.async.commit_group;" ::: "memory")
#define CP_WAIT(n)  asm volatile("cp.async.wait_group %0;" :: "n"(n) : "memory")

__device__ __forceinline__ uint32_t pack_bf16x2(float a, float b) {
    uint32_t r;
    asm("cvt.rn.bf16x2.f32 %0, %1, %2;" : "=r"(r) : "f"(b), "f"(a));  // lo=a, hi=b
    return r;
}
// given hpair = {bf16rn(f1):bf16rn(f0)}, build lo-pair = {rn(f1-h1):rn(f0-h0)}
__device__ __forceinline__ uint32_t lo_from_pair(uint32_t hpair, float f0, float f1) {
    float fh0 = __uint_as_float(hpair << 16);
    float fh1 = __uint_as_float(hpair & 0xffff0000u);
    return pack_bf16x2(f0 - fh0, f1 - fh1);
}

// ---------------------------------------------------------------------------
// Kernel 0: split proj (D,R) fp32 -> projT hi/lo (R,D) bf16 (rn split),
// coalesced via smem transpose. Grid (32 k-tiles, 2 r-tiles), 256 thr, 32x64.
// ---------------------------------------------------------------------------
__global__ __launch_bounds__(256) void prep_proj_kernel(const float* __restrict__ proj) {
    __shared__ float sT[32][65];
    const int tid = threadIdx.x;
    const int k0 = blockIdx.x * 32;
    const int r0 = blockIdx.y * 64;

#pragma unroll
    for (int t = 0; t < 4; ++t) {
        const int idx = tid + t * 256;           // 1024 float2 chunks
        const int k = idx >> 5, c2 = idx & 31;
        float2 v = *reinterpret_cast<const float2*>(proj + (size_t)(k0 + k) * RR + r0 + c2 * 2);
        sT[k][c2 * 2] = v.x;
        sT[k][c2 * 2 + 1] = v.y;
    }
    __syncthreads();

#pragma unroll
    for (int t = 0; t < 2; ++t) {
        const int idx = tid + t * 256;           // 512 4-elem chunks (64 r x 8 kq)
        const int r = idx >> 3, kq = idx & 7;
        float f[4];
#pragma unroll
        for (int e = 0; e < 4; ++e) f[e] = sT[kq * 4 + e][r];
        uint2 hv, lv;
        hv.x = pack_bf16x2(f[0], f[1]);
        hv.y = pack_bf16x2(f[2], f[3]);
        lv.x = lo_from_pair(hv.x, f[0], f[1]);
        lv.y = lo_from_pair(hv.y, f[2], f[3]);
        const size_t o = (size_t)(r0 + r) * DD + k0 + kq * 4;
        *reinterpret_cast<uint2*>(g_pT_hi + o) = hv;
        *reinterpret_cast<uint2*>(g_pT_lo + o) = lv;
    }
}

// ---------------------------------------------------------------------------
// Kernel 1: T = batch @ proj (16384x128, K=1024), 2-term mma.sync:
//   T ~= Ah*Bh + Ah*Bl   (A rounded once to bf16-rn; B rn-split hi/lo)
// 128 thr (4 warps), CTA tile 64x128, BK=32, warp tile 16x128, grid 256.
// Double-buffered dynamic smem (2 x 25KB); B via cp.async, A via reg pipeline.
// ---------------------------------------------------------------------------
#define S1B 80                       // bytes per smem row
#define A_ARR (64 * S1B)             // 5120
#define B_ARR (128 * S1B)            // 10240
#define G1_BUF (A_ARR + 2 * B_ARR)   // 25600
#define G1_SMEM (2 * G1_BUF)         // 51200

__global__ __launch_bounds__(128) void gemm1_kernel(const float* __restrict__ batch) {
    extern __shared__ __align__(16) char sm1[];
    const uint32_t base = smem_u32(sm1);

    const int tid = threadIdx.x;
    const int wid = tid >> 5;
    const int lane = tid & 31;
    const int row0 = blockIdx.x * 64;

    const int a_row = tid >> 3, a_k4 = tid & 7;   // A: 64 rows x 8 float4 (x4 steps of 16)

    const uint32_t a_off = (uint32_t)((wid * 16 + (lane & 15)) * S1B + ((lane >> 4) & 1) * 16);
    const uint32_t b_off = (uint32_t)(((lane & 7) + ((lane >> 4) & 1) * 8) * S1B + ((lane >> 3) & 1) * 16);

    float acc[16][4];
#pragma unroll
    for (int i = 0; i < 16; i++)
#pragma unroll
        for (int j = 0; j < 4; j++) acc[i][j] = 0.0f;

    float4 pfa[4];

    // ---- prologue: iter 0 ----
#pragma unroll
    for (int i = 0; i < 4; i++)
        pfa[i] = *reinterpret_cast<const float4*>(
            batch + (size_t)(row0 + a_row + i * 16) * DD + a_k4 * 4);
    {
        const uint32_t bb = base;
#pragma unroll
        for (int t = 0; t < 4; ++t) {
            const int c = tid + t * 128;       // 512 chunks per B array
            const int row = c >> 2, kc = c & 3;
            const uint32_t off = (uint32_t)(row * S1B + kc * 16);
            CP16(bb + A_ARR + off, g_pT_hi + (size_t)row * DD + kc * 8);
            CP16(bb + A_ARR + B_ARR + off, g_pT_lo + (size_t)row * DD + kc * 8);
        }
        CP_COMMIT();
#pragma unroll
        for (int i = 0; i < 4; i++) {
            float4 v = pfa[i];
            uint32_t h01 = pack_bf16x2(v.x, v.y);
            uint32_t h23 = pack_bf16x2(v.z, v.w);
            const uint32_t off = (uint32_t)((a_row + i * 16) * S1B + a_k4 * 8);
            asm volatile("st.shared.v2.b32 [%0], {%1,%2};" :: "r"(bb + off), "r"(h01), "r"(h23) : "memory");
        }
    }
    CP_WAIT(0);
    __syncthreads();

    for (int it = 0; it < 32; ++it) {
        const int p = it & 1;
        const uint32_t bb = base + p * G1_BUF;
        const uint32_t nb = base + (p ^ 1) * G1_BUF;

        if (it < 31) {
            const int k0n = (it + 1) * 32;
#pragma unroll
            for (int t = 0; t < 4; ++t) {
                const int c = tid + t * 128;
                const int row = c >> 2, kc = c & 3;
                const uint32_t off = (uint32_t)(row * S1B + kc * 16);
                CP16(nb + A_ARR + off, g_pT_hi + (size_t)row * DD + k0n + kc * 8);
                CP16(nb + A_ARR + B_ARR + off, g_pT_lo + (size_t)row * DD + k0n + kc * 8);
            }
            CP_COMMIT();
#pragma unroll
            for (int i = 0; i < 4; i++)
                pfa[i] = *reinterpret_cast<const float4*>(
                    batch + (size_t)(row0 + a_row + i * 16) * DD + k0n + a_k4 * 4);
        }

        // compute on buffer p: 2 k16 steps, 2-term
#pragma unroll
        for (int s = 0; s < 2; ++s) {
            uint32_t Ah[4];
            ldsm4(Ah, bb + a_off + s * 32);
#pragma unroll
            for (int nt = 0; nt < 8; ++nt) {
                uint32_t Bh4[4], Bl4[4];
                ldsm4(Bh4, bb + A_ARR + b_off + nt * (16 * S1B) + s * 32);
                ldsm4(Bl4, bb + A_ARR + B_ARR + b_off + nt * (16 * S1B) + s * 32);
                mma_bf16(acc[nt * 2 + 0], Ah, Bh4[0], Bh4[1]);
                mma_bf16(acc[nt * 2 + 1], Ah, Bh4[2], Bh4[3]);
                mma_bf16(acc[nt * 2 + 0], Ah, Bl4[0], Bl4[1]);
                mma_bf16(acc[nt * 2 + 1], Ah, Bl4[2], Bl4[3]);
            }
        }

        if (it < 31) {
#pragma unroll
            for (int i = 0; i < 4; i++) {
                float4 v = pfa[i];
                uint32_t h01 = pack_bf16x2(v.x, v.y);
                uint32_t h23 = pack_bf16x2(v.z, v.w);
                const uint32_t off = (uint32_t)((a_row + i * 16) * S1B + a_k4 * 8);
                asm volatile("st.shared.v2.b32 [%0], {%1,%2};" :: "r"(nb + off), "r"(h01), "r"(h23) : "memory");
            }
            CP_WAIT(0);
        }
        __syncthreads();
    }

    // Epilogue: warp-private rows r0 = row0 + wid*16 + lane>>2, r1 = r0+8.
    const int r0g = row0 + wid * 16 + (lane >> 2);
    const int r1g = r0g + 8;
    uint32_t* thi32 = reinterpret_cast<uint32_t*>(g_thi);
    uint32_t* tlo32 = reinterpret_cast<uint32_t*>(g_tlo);
    float sq0 = 0.0f, sq1 = 0.0f;
#pragma unroll
    for (int nt = 0; nt < 16; ++nt) {
        const int cidx = nt * 4 + (lane & 3);
        float f0 = acc[nt][0], f1 = acc[nt][1], f2 = acc[nt][2], f3 = acc[nt][3];
        sq0 = fmaf(f0, f0, sq0); sq0 = fmaf(f1, f1, sq0);
        sq1 = fmaf(f2, f2, sq1); sq1 = fmaf(f3, f3, sq1);
        uint32_t h01 = pack_bf16x2(f0, f1);
        uint32_t h23 = pack_bf16x2(f2, f3);
        thi32[(size_t)r0g * 64 + cidx] = h01;
        thi32[(size_t)r1g * 64 + cidx] = h23;
        tlo32[(size_t)r0g * 64 + cidx] = lo_from_pair(h01, f0, f1);
        tlo32[(size_t)r1g * 64 + cidx] = lo_from_pair(h23, f2, f3);
    }
#pragma unroll
    for (int o = 1; o <= 2; o <<= 1) {
        sq0 += __shfl_xor_sync(0xffffffffu, sq0, o);
        sq1 += __shfl_xor_sync(0xffffffffu, sq1, o);
    }
    if ((lane & 3) == 0) { g_sqn[r0g] = sq0; g_sqn[r1g] = sq1; }
}

// ---------------------------------------------------------------------------
// Kernel 2: symmetric Gram tiles, 2-term: c = Thi_i * (Thj + Tlj).
// Grid (10 tile-pairs, 32 batches), 3 smem tiles (Ah, Bh, Bl), 2 CTAs/SM.
// Off-diagonal mirror via conflict-free smem transpose. Split-K cp.async.
// ---------------------------------------------------------------------------
#define S2B 272                        // bytes per smem row (136 bf16)
#define G2_TILE (128 * S2B)            // 34816
#define G2_SMEM (3 * G2_TILE + 1024)   // 105472

__global__ __launch_bounds__(256, 2) void gemm2_kernel(float* __restrict__ out) {
    extern __shared__ __align__(16) char sm2[];
    const uint32_t ah = smem_u32(sm2);
    const uint32_t bh = ah + G2_TILE;
    const uint32_t bl = ah + 2 * G2_TILE;
    float* sNi = reinterpret_cast<float*>(sm2 + 3 * G2_TILE);
    float* sNj = sNi + 128;
    float* sD  = reinterpret_cast<float*>(sm2);   // transpose staging (aliases Ah+Bh)

    const int tid = threadIdx.x;
    const int wid = tid >> 5;
    const int lane = tid & 31;
    const int b = blockIdx.y;
    const int ti = c_ti[blockIdx.x], tj = c_tj[blockIdx.x];
    const bool diag = (ti == tj);
    const int i0 = ti * 128, j0 = tj * 128;

    const __nv_bfloat16* srcs[3] = {
        g_thi + (size_t)(b * LL + i0) * RR,   // -> ah
        g_tlo + (size_t)(b * LL + j0) * RR,   // -> bl
        g_thi + (size_t)(b * LL + j0) * RR }; // -> bh (off-diag only)
    const uint32_t dsts[3] = { ah, bl, bh };
    const int ntile = diag ? 2 : 3;

    // Split-K cp.async: group 0 = k[0,64), group 1 = k[64,128)
#pragma unroll
    for (int h = 0; h < 2; ++h) {
        for (int r = 0; r < ntile; ++r) {
#pragma unroll
            for (int q = 0; q < 4; ++q) {
                const int idx = tid + q * 256;           // 1024 chunks per half-tile
                const int row = idx >> 3, kcl = idx & 7;
                const int kc = h * 8 + kcl;
                CP16(dsts[r] + (uint32_t)(row * S2B + kc * 16),
                     srcs[r] + (size_t)row * RR + kc * 8);
            }
        }
        CP_COMMIT();
    }
    if (tid < 128) sNi[tid] = g_sqn[b * LL + i0 + tid];
    else sNj[tid - 128] = g_sqn[b * LL + j0 + (tid - 128)];

    const uint32_t bhc = diag ? ah : bh;
    const uint32_t a_off = (uint32_t)((wid * 16 + (lane & 15)) * S2B + ((lane >> 4) & 1) * 16);
    const uint32_t b_off = (uint32_t)(((lane & 7) + ((lane >> 4) & 1) * 8) * S2B + ((lane >> 3) & 1) * 16);

    float acc[16][4];
#pragma unroll
    for (int i = 0; i < 16; i++)
#pragma unroll
        for (int j = 0; j < 4; j++) acc[i][j] = 0.0f;

    CP_WAIT(1);
    __syncthreads();

#pragma unroll
    for (int s = 0; s < 8; ++s) {
        if (s == 4) { CP_WAIT(0); __syncthreads(); }
        uint32_t Ah[4];
        ldsm4(Ah, ah + a_off + s * 32);
#pragma unroll
        for (int nt = 0; nt < 8; ++nt) {
            uint32_t Bh4[4], Bl4[4];
            ldsm4(Bh4, bhc + b_off + nt * (16 * S2B) + s * 32);
            ldsm4(Bl4, bl + b_off + nt * (16 * S2B) + s * 32);
            mma_bf16(acc[nt * 2 + 0], Ah, Bh4[0], Bh4[1]);
            mma_bf16(acc[nt * 2 + 1], Ah, Bh4[2], Bh4[3]);
            mma_bf16(acc[nt * 2 + 0], Ah, Bl4[0], Bl4[1]);
            mma_bf16(acc[nt * 2 + 1], Ah, Bl4[2], Bl4[3]);
        }
    }
    __syncthreads();   // all ldsm done before sD overwrites tile smem

    // Epilogue: direct store of (i,j) block; stage transposed copy for mirror.
    const int r0l = wid * 16 + (lane >> 2);
    const float ni0 = sNi[r0l], ni1 = sNi[r0l + 8];
    float* o0 = out + ((size_t)(b * LL + i0 + r0l)) * LL + j0;
    float* o1 = o0 + 8 * LL;
#pragma unroll
    for (int nt = 0; nt < 16; ++nt) {
        const int col = nt * 8 + (lane & 3) * 2;
        const float nj0 = sNj[col], nj1 = sNj[col + 1];
        float2 v0, v1;
        v0.x = fmaxf(ni0 + nj0 - 2.0f * acc[nt][0], 0.0f);
        v0.y = fmaxf(ni0 + nj1 - 2.0f * acc[nt][1], 0.0f);
        v1.x = fmaxf(ni1 + nj0 - 2.0f * acc[nt][2], 0.0f);
        v1.y = fmaxf(ni1 + nj1 - 2.0f * acc[nt][3], 0.0f);
        *reinterpret_cast<float2*>(o0 + col) = v0;
        *reinterpret_cast<float2*>(o1 + col) = v1;
        if (!diag) {
            sD[col * 132 + r0l]           = v0.x;   // sD_T[c][r]
            sD[(col + 1) * 132 + r0l]     = v0.y;
            sD[col * 132 + r0l + 8]       = v1.x;
            sD[(col + 1) * 132 + r0l + 8] = v1.y;
        }
    }
    if (!diag) {
        __syncthreads();
#pragma unroll
        for (int t = 0; t < 16; ++t) {
            const int idx = tid + t * 256;
            const int tr = idx >> 5;                 // transposed row = orig col
            float4 v = *reinterpret_cast<const float4*>(sD + (size_t)tr * 132 + lane * 4);
            *reinterpret_cast<float4*>(
                out + ((size_t)(b * LL + j0 + tr)) * LL + i0 + lane * 4) = v;
        }
    }
}

extern "C" void kernel_launch(void* const* d_in, const int* in_sizes, int n_in,
                              void* d_out, int out_size)
{
    const float* batch = (const float*)d_in[0];  // (32, 512, 1024) f32
    const float* proj  = (const float*)d_in[1];  // (1024, 128) f32
    float* out = (float*)d_out;                  // (32, 512, 512) f32

    cudaFuncSetAttribute(gemm1_kernel, cudaFuncAttributeMaxDynamicSharedMemorySize, G1_SMEM);
    cudaFuncSetAttribute(gemm2_kernel, cudaFuncAttributeMaxDynamicSharedMemorySize, G2_SMEM);

    prep_proj_kernel<<<dim3(32, 2), 256>>>(proj);
    gemm1_kernel<<<M_TOTAL / 64, 128, G1_SMEM>>>(batch);
    gemm2_kernel<<<dim3(10, BB), 256, G2_SMEM>>>(out);
}

// round 13
// speedup vs baseline: 3.5105x; 1.2130x over previous
#include <cuda_runtime.h>
#include <cuda_bf16.h>
#include <cstdint>

#define BB 32
#define LL 512
#define DD 1024
#define RR 128
#define M_TOTAL (BB * LL)   // 16384

// ---------------- global scratch ----------------
__device__ __align__(16) __nv_bfloat16 g_pT_hi[RR * DD];     // projT hi [128][1024]
__device__ __align__(16) __nv_bfloat16 g_pT_lo[RR * DD];     // projT lo
__device__ __align__(16) __nv_bfloat16 g_thi[M_TOTAL * RR];  // T hi [16384][128]
__device__ __align__(16) __nv_bfloat16 g_tlo[M_TOTAL * RR];  // T lo
__device__ float g_sqn[M_TOTAL];

__constant__ int c_ti[10] = {0,0,0,0,1,1,1,2,2,3};
__constant__ int c_tj[10] = {0,1,2,3,1,2,3,2,3,3};

// ---------------- helpers (arch-feature-free PTX only) ----------------
__device__ __forceinline__ uint32_t smem_u32(const void* p) {
    uint32_t a;
    asm("{ .reg .u64 t; cvta.to.shared.u64 t, %1; cvt.u32.u64 %0, t; }" : "=r"(a) : "l"(p));
    return a;
}
__device__ __forceinline__ void ldsm4(uint32_t r[4], uint32_t addr) {
    asm volatile("ldmatrix.sync.aligned.m8n8.x4.shared.b16 {%0,%1,%2,%3}, [%4];"
                 : "=r"(r[0]), "=r"(r[1]), "=r"(r[2]), "=r"(r[3]) : "r"(addr));
}
__device__ __forceinline__ void mma_bf16(float d[4], const uint32_t a[4],
                                         uint32_t b0, uint32_t b1) {
    asm volatile(
        "mma.sync.aligned.m16n8k16.row.col.f32.bf16.bf16.f32 "
        "{%0,%1,%2,%3},{%4,%5,%6,%7},{%8,%9},{%0,%1,%2,%3};"
        : "+f"(d[0]), "+f"(d[1]), "+f"(d[2]), "+f"(d[3])
        : "r"(a[0]), "r"(a[1]), "r"(a[2]), "r"(a[3]), "r"(b0), "r"(b1));
}
#define CP16(dst, src) \
    asm volatile("cp.async.cg.shared.global [%0], [%1], 16;" :: "r"(dst), "l"(src) : "memory")
#define CP_COMMIT() asm volatile("cp.async.commit_group;" ::: "memory")
#define CP_WAIT(n)  asm volatile("cp.async.wait_group %0;" :: "n"(n) : "memory")

__device__ __forceinline__ uint32_t pack_bf16x2(float a, float b) {
    uint32_t r;
    asm("cvt.rn.bf16x2.f32 %0, %1, %2;" : "=r"(r) : "f"(b), "f"(a));  // lo=a, hi=b
    return r;
}
__device__ __forceinline__ uint32_t lo_from_pair(uint32_t hpair, float f0, float f1) {
    float fh0 = __uint_as_float(hpair << 16);
    float fh1 = __uint_as_float(hpair & 0xffff0000u);
    return pack_bf16x2(f0 - fh0, f1 - fh1);
}

// ---------------------------------------------------------------------------
// Kernel 0: split proj (D,R) fp32 -> projT hi/lo (R,D) bf16 (rn split).
// Grid (32 k-tiles, 4 r-tiles), 256 thr, 32x32 tiles.
// ---------------------------------------------------------------------------
__global__ __launch_bounds__(256) void prep_proj_kernel(const float* __restrict__ proj) {
    __shared__ float sT[32][33];
    const int tid = threadIdx.x;
    const int k0 = blockIdx.x * 32;
    const int r0 = blockIdx.y * 32;

#pragma unroll
    for (int t = 0; t < 2; ++t) {
        const int idx = tid + t * 256;           // 512 float2 chunks
        const int k = idx >> 4, c2 = idx & 15;
        float2 v = *reinterpret_cast<const float2*>(proj + (size_t)(k0 + k) * RR + r0 + c2 * 2);
        sT[k][c2 * 2] = v.x;
        sT[k][c2 * 2 + 1] = v.y;
    }
    __syncthreads();

    {
        const int r = tid >> 3, kq = tid & 7;    // 32 r x 8 kq
        float f[4];
#pragma unroll
        for (int e = 0; e < 4; ++e) f[e] = sT[kq * 4 + e][r];
        uint2 hv, lv;
        hv.x = pack_bf16x2(f[0], f[1]);
        hv.y = pack_bf16x2(f[2], f[3]);
        lv.x = lo_from_pair(hv.x, f[0], f[1]);
        lv.y = lo_from_pair(hv.y, f[2], f[3]);
        const size_t o = (size_t)(r0 + r) * DD + k0 + kq * 4;
        *reinterpret_cast<uint2*>(g_pT_hi + o) = hv;
        *reinterpret_cast<uint2*>(g_pT_lo + o) = lv;
    }
}

// ---------------------------------------------------------------------------
// Kernel 1: T = batch @ proj (16384x128, K=1024), 2-term mma.sync:
//   T ~= Ah*Bh + Ah*Bl
// 256 thr (8 warps = 2/SMSP), CTA tile 64x128, BK=64 (16 iters), warp 16x64.
// XOR-swizzled 128B smem rows (conflict-free ldmatrix, aligned cp.async).
// Double-buffered (2 x 40KB). Grid 256 = one wave at 2 CTAs/SM.
// ---------------------------------------------------------------------------
#define A_ARR 8192                   // 64 rows x 128B
#define B_ARR 16384                  // 128 rows x 128B
#define G1_BUF (A_ARR + 2 * B_ARR)   // 40960
#define G1_SMEM (2 * G1_BUF)         // 81920

__global__ __launch_bounds__(256) void gemm1_kernel(const float* __restrict__ batch) {
    extern __shared__ __align__(16) char sm1[];
    __shared__ float sSq[64][2];
    const uint32_t base = smem_u32(sm1);

    const int tid = threadIdx.x;
    const int wid = tid >> 5;
    const int lane = tid & 31;
    const int row0 = blockIdx.x * 64;
    const int wm = (wid & 3) * 16;      // M group within 64
    const int wn = (wid >> 2) * 64;     // N half within 128

    // loader maps
    const int a_row = tid >> 4, a_k4 = tid & 15;  // A: 64 rows x 16 float4 (fp32)
    const int b_row = tid >> 3, b_c = tid & 7;    // B: 128 rows x 8 16B-chunks

    // swizzled A STS offset pieces: chunk c = k4>>1, +8B if k4 odd
    const uint32_t a_sts = (uint32_t)(a_row * 128 + (((a_k4 >> 1) ^ (a_row & 7)) << 4) + (a_k4 & 1) * 8);
    const uint32_t b_cp  = (uint32_t)(b_row * 128 + ((b_c ^ (b_row & 7)) << 4));

    // ldmatrix lane pieces
    const int a_lrow = wm + (lane & 15);
    const uint32_t a_rowbase = (uint32_t)(a_lrow * 128);
    const int a_x = a_lrow & 7;
    const int a_bit = (lane >> 4) & 1;
    const int b_lrow_loc = (lane & 7) + ((lane >> 4) & 1) * 8;   // within 16-row nt group
    const int b_x = lane & 7;
    const int b_bit = (lane >> 3) & 1;

    float acc[8][4];
#pragma unroll
    for (int i = 0; i < 8; i++)
#pragma unroll
        for (int j = 0; j < 4; j++) acc[i][j] = 0.0f;

    float4 pfa[4];

    // ---- prologue: iter 0 ----
#pragma unroll
    for (int i = 0; i < 4; i++)
        pfa[i] = *reinterpret_cast<const float4*>(
            batch + (size_t)(row0 + a_row + i * 16) * DD + a_k4 * 4);
    {
        const uint32_t bb = base;
#pragma unroll
        for (int t = 0; t < 4; ++t) {
            const int row = b_row + t * 32;
            const uint32_t off = b_cp + (uint32_t)(t * 32 * 128);
            CP16(bb + A_ARR + off, g_pT_hi + (size_t)row * DD + b_c * 8);
            CP16(bb + A_ARR + B_ARR + off, g_pT_lo + (size_t)row * DD + b_c * 8);
        }
        CP_COMMIT();
#pragma unroll
        for (int i = 0; i < 4; i++) {
            float4 v = pfa[i];
            uint32_t h01 = pack_bf16x2(v.x, v.y);
            uint32_t h23 = pack_bf16x2(v.z, v.w);
            asm volatile("st.shared.v2.b32 [%0], {%1,%2};"
                :: "r"(bb + a_sts + (uint32_t)(i * 16 * 128)), "r"(h01), "r"(h23) : "memory");
        }
    }
    CP_WAIT(0);
    __syncthreads();

    for (int it = 0; it < 16; ++it) {
        const int p = it & 1;
        const uint32_t bb = base + p * G1_BUF;
        const uint32_t nb = base + (p ^ 1) * G1_BUF;

        if (it < 15) {
            const int k0n = (it + 1) * 64;
#pragma unroll
            for (int t = 0; t < 4; ++t) {
                const int row = b_row + t * 32;
                const uint32_t off = b_cp + (uint32_t)(t * 32 * 128);
                CP16(nb + A_ARR + off, g_pT_hi + (size_t)row * DD + k0n + b_c * 8);
                CP16(nb + A_ARR + B_ARR + off, g_pT_lo + (size_t)row * DD + k0n + b_c * 8);
            }
            CP_COMMIT();
#pragma unroll
            for (int i = 0; i < 4; i++)
                pfa[i] = *reinterpret_cast<const float4*>(
                    batch + (size_t)(row0 + a_row + i * 16) * DD + k0n + a_k4 * 4);
        }

        // compute on buffer p: 4 k16 steps, 2-term, warp tile 16x64
#pragma unroll
        for (int s = 0; s < 4; ++s) {
            uint32_t Ah[4];
            ldsm4(Ah, bb + a_rowbase + (uint32_t)((((2 * s + a_bit) ^ a_x) << 4)));
#pragma unroll
            for (int nt = 0; nt < 4; ++nt) {
                const uint32_t brb = (uint32_t)((wn + nt * 16 + b_lrow_loc) * 128);
                const uint32_t bsw = (uint32_t)(((2 * s + b_bit) ^ b_x) << 4);
                uint32_t Bh4[4], Bl4[4];
                ldsm4(Bh4, bb + A_ARR + brb + bsw);
                ldsm4(Bl4, bb + A_ARR + B_ARR + brb + bsw);
                mma_bf16(acc[nt * 2 + 0], Ah, Bh4[0], Bh4[1]);
                mma_bf16(acc[nt * 2 + 1], Ah, Bh4[2], Bh4[3]);
                mma_bf16(acc[nt * 2 + 0], Ah, Bl4[0], Bl4[1]);
                mma_bf16(acc[nt * 2 + 1], Ah, Bl4[2], Bl4[3]);
            }
        }

        if (it < 15) {
#pragma unroll
            for (int i = 0; i < 4; i++) {
                float4 v = pfa[i];
                uint32_t h01 = pack_bf16x2(v.x, v.y);
                uint32_t h23 = pack_bf16x2(v.z, v.w);
                asm volatile("st.shared.v2.b32 [%0], {%1,%2};"
                    :: "r"(nb + a_sts + (uint32_t)(i * 16 * 128)), "r"(h01), "r"(h23) : "memory");
            }
            CP_WAIT(0);
        }
        __syncthreads();
    }

    // Epilogue: rows r0 = row0+wm+(lane>>2), r1 = r0+8; cols [wn, wn+64).
    const int r0g = row0 + wm + (lane >> 2);
    const int r1g = r0g + 8;
    uint32_t* thi32 = reinterpret_cast<uint32_t*>(g_thi);
    uint32_t* tlo32 = reinterpret_cast<uint32_t*>(g_tlo);
    float sq0 = 0.0f, sq1 = 0.0f;
#pragma unroll
    for (int nt = 0; nt < 4; ++nt) {
#pragma unroll
        for (int h = 0; h < 2; ++h) {
            float f0 = acc[nt * 2 + h][0], f1 = acc[nt * 2 + h][1];
            float f2 = acc[nt * 2 + h][2], f3 = acc[nt * 2 + h][3];
            sq0 = fmaf(f0, f0, sq0); sq0 = fmaf(f1, f1, sq0);
            sq1 = fmaf(f2, f2, sq1); sq1 = fmaf(f3, f3, sq1);
            const int cidx = wn / 2 + nt * 8 + h * 4 + (lane & 3);
            uint32_t h01 = pack_bf16x2(f0, f1);
            uint32_t h23 = pack_bf16x2(f2, f3);
            thi32[(size_t)r0g * 64 + cidx] = h01;
            thi32[(size_t)r1g * 64 + cidx] = h23;
            tlo32[(size_t)r0g * 64 + cidx] = lo_from_pair(h01, f0, f1);
            tlo32[(size_t)r1g * 64 + cidx] = lo_from_pair(h23, f2, f3);
        }
    }
#pragma unroll
    for (int o = 1; o <= 2; o <<= 1) {
        sq0 += __shfl_xor_sync(0xffffffffu, sq0, o);
        sq1 += __shfl_xor_sync(0xffffffffu, sq1, o);
    }
    const int whalf = wid >> 2;
    if ((lane & 3) == 0) {
        sSq[wm + (lane >> 2)][whalf] = sq0;
        sSq[wm + 8 + (lane >> 2)][whalf] = sq1;
    }
    __syncthreads();
    if (tid < 64) g_sqn[row0 + tid] = sSq[tid][0] + sSq[tid][1];
}

// ---------------------------------------------------------------------------
// Kernel 2: symmetric Gram tiles, 2-term: c = Thi_i * (Thj + Tlj).
// Grid (10 tile-pairs, 32 batches), 3 smem tiles (Ah, Bh, Bl), 2 CTAs/SM.
// Off-diagonal mirror via conflict-free smem transpose. Split-K cp.async.
// ---------------------------------------------------------------------------
#define S2B 272                        // bytes per smem row (136 bf16)
#define G2_TILE (128 * S2B)            // 34816
#define G2_SMEM (3 * G2_TILE + 1024)   // 105472

__global__ __launch_bounds__(256, 2) void gemm2_kernel(float* __restrict__ out) {
    extern __shared__ __align__(16) char sm2[];
    const uint32_t ah = smem_u32(sm2);
    const uint32_t bh = ah + G2_TILE;
    const uint32_t bl = ah + 2 * G2_TILE;
    float* sNi = reinterpret_cast<float*>(sm2 + 3 * G2_TILE);
    float* sNj = sNi + 128;
    float* sD  = reinterpret_cast<float*>(sm2);   // transpose staging (aliases Ah+Bh)

    const int tid = threadIdx.x;
    const int wid = tid >> 5;
    const int lane = tid & 31;
    const int b = blockIdx.y;
    const int ti = c_ti[blockIdx.x], tj = c_tj[blockIdx.x];
    const bool diag = (ti == tj);
    const int i0 = ti * 128, j0 = tj * 128;

    const __nv_bfloat16* srcs[3] = {
        g_thi + (size_t)(b * LL + i0) * RR,   // -> ah
        g_tlo + (size_t)(b * LL + j0) * RR,   // -> bl
        g_thi + (size_t)(b * LL + j0) * RR }; // -> bh (off-diag only)
    const uint32_t dsts[3] = { ah, bl, bh };
    const int ntile = diag ? 2 : 3;

    // Split-K cp.async: group 0 = k[0,64), group 1 = k[64,128)
#pragma unroll
    for (int h = 0; h < 2; ++h) {
        for (int r = 0; r < ntile; ++r) {
#pragma unroll
            for (int q = 0; q < 4; ++q) {
                const int idx = tid + q * 256;           // 1024 chunks per half-tile
                const int row = idx >> 3, kcl = idx & 7;
                const int kc = h * 8 + kcl;
                CP16(dsts[r] + (uint32_t)(row * S2B + kc * 16),
                     srcs[r] + (size_t)row * RR + kc * 8);
            }
        }
        CP_COMMIT();
    }
    if (tid < 128) sNi[tid] = g_sqn[b * LL + i0 + tid];
    else sNj[tid - 128] = g_sqn[b * LL + j0 + (tid - 128)];

    const uint32_t bhc = diag ? ah : bh;
    const uint32_t a_off = (uint32_t)((wid * 16 + (lane & 15)) * S2B + ((lane >> 4) & 1) * 16);
    const uint32_t b_off = (uint32_t)(((lane & 7) + ((lane >> 4) & 1) * 8) * S2B + ((lane >> 3) & 1) * 16);

    float acc[16][4];
#pragma unroll
    for (int i = 0; i < 16; i++)
#pragma unroll
        for (int j = 0; j < 4; j++) acc[i][j] = 0.0f;

    CP_WAIT(1);
    __syncthreads();

#pragma unroll
    for (int s = 0; s < 8; ++s) {
        if (s == 4) { CP_WAIT(0); __syncthreads(); }
        uint32_t Ah[4];
        ldsm4(Ah, ah + a_off + s * 32);
#pragma unroll
        for (int nt = 0; nt < 8; ++nt) {
            uint32_t Bh4[4], Bl4[4];
            ldsm4(Bh4, bhc + b_off + nt * (16 * S2B) + s * 32);
            ldsm4(Bl4, bl + b_off + nt * (16 * S2B) + s * 32);
            mma_bf16(acc[nt * 2 + 0], Ah, Bh4[0], Bh4[1]);
            mma_bf16(acc[nt * 2 + 1], Ah, Bh4[2], Bh4[3]);
            mma_bf16(acc[nt * 2 + 0], Ah, Bl4[0], Bl4[1]);
            mma_bf16(acc[nt * 2 + 1], Ah, Bl4[2], Bl4[3]);
        }
    }
    __syncthreads();   // all ldsm done before sD overwrites tile smem

    // Epilogue: direct store of (i,j) block; stage transposed copy for mirror.
    const int r0l = wid * 16 + (lane >> 2);
    const float ni0 = sNi[r0l], ni1 = sNi[r0l + 8];
    float* o0 = out + ((size_t)(b * LL + i0 + r0l)) * LL + j0;
    float* o1 = o0 + 8 * LL;
#pragma unroll
    for (int nt = 0; nt < 16; ++nt) {
        const int col = nt * 8 + (lane & 3) * 2;
        const float nj0 = sNj[col], nj1 = sNj[col + 1];
        float2 v0, v1;
        v0.x = fmaxf(ni0 + nj0 - 2.0f * acc[nt][0], 0.0f);
        v0.y = fmaxf(ni0 + nj1 - 2.0f * acc[nt][1], 0.0f);
        v1.x = fmaxf(ni1 + nj0 - 2.0f * acc[nt][2], 0.0f);
        v1.y = fmaxf(ni1 + nj1 - 2.0f * acc[nt][3], 0.0f);
        *reinterpret_cast<float2*>(o0 + col) = v0;
        *reinterpret_cast<float2*>(o1 + col) = v1;
        if (!diag) {
            sD[col * 132 + r0l]           = v0.x;   // sD_T[c][r]
            sD[(col + 1) * 132 + r0l]     = v0.y;
            sD[col * 132 + r0l + 8]       = v1.x;
            sD[(col + 1) * 132 + r0l + 8] = v1.y;
        }
    }
    if (!diag) {
        __syncthreads();
#pragma unroll
        for (int t = 0; t < 16; ++t) {
            const int idx = tid + t * 256;
            const int tr = idx >> 5;                 // transposed row = orig col
            float4 v = *reinterpret_cast<const float4*>(sD + (size_t)tr * 132 + lane * 4);
            *reinterpret_cast<float4*>(
                out + ((size_t)(b * LL + j0 + tr)) * LL + i0 + lane * 4) = v;
        }
    }
}

extern "C" void kernel_launch(void* const* d_in, const int* in_sizes, int n_in,
                              void* d_out, int out_size)
{
    const float* batch = (const float*)d_in[0];  // (32, 512, 1024) f32
    const float* proj  = (const float*)d_in[1];  // (1024, 128) f32
    float* out = (float*)d_out;                  // (32, 512, 512) f32

    cudaFuncSetAttribute(gemm1_kernel, cudaFuncAttributeMaxDynamicSharedMemorySize, G1_SMEM);
    cudaFuncSetAttribute(gemm2_kernel, cudaFuncAttributeMaxDynamicSharedMemorySize, G2_SMEM);

    prep_proj_kernel<<<dim3(32, 4), 256>>>(proj);
    gemm1_kernel<<<M_TOTAL / 64, 256, G1_SMEM>>>(batch);
    gemm2_kernel<<<dim3(10, BB), 256, G2_SMEM>>>(out);
}

// round 15
// speedup vs baseline: 3.7249x; 1.0611x over previous
#include <cuda_runtime.h>
#include <cuda_bf16.h>
#include <cstdint>

#define BB 32
#define LL 512
#define DD 1024
#define RR 128
#define M_TOTAL (BB * LL)   // 16384

// ---------------- global scratch ----------------
__device__ __align__(16) __nv_bfloat16 g_pT_hi[RR * DD];     // projT hi [128][1024]
__device__ __align__(16) __nv_bfloat16 g_pT_lo[RR * DD];     // projT lo
__device__ __align__(16) __nv_bfloat16 g_thi[M_TOTAL * RR];  // T hi [16384][128]
__device__ __align__(16) __nv_bfloat16 g_tlo[M_TOTAL * RR];  // T lo
__device__ float g_sqn[M_TOTAL];

__constant__ int c_ti[10] = {0,0,0,0,1,1,1,2,2,3};
__constant__ int c_tj[10] = {0,1,2,3,1,2,3,2,3,3};

// ---------------- helpers (arch-feature-free PTX only) ----------------
__device__ __forceinline__ uint32_t smem_u32(const void* p) {
    uint32_t a;
    asm("{ .reg .u64 t; cvta.to.shared.u64 t, %1; cvt.u32.u64 %0, t; }" : "=r"(a) : "l"(p));
    return a;
}
__device__ __forceinline__ void ldsm4(uint32_t r[4], uint32_t addr) {
    asm volatile("ldmatrix.sync.aligned.m8n8.x4.shared.b16 {%0,%1,%2,%3}, [%4];"
                 : "=r"(r[0]), "=r"(r[1]), "=r"(r[2]), "=r"(r[3]) : "r"(addr));
}
__device__ __forceinline__ void mma_bf16(float d[4], const uint32_t a[4],
                                         uint32_t b0, uint32_t b1) {
    asm volatile(
        "mma.sync.aligned.m16n8k16.row.col.f32.bf16.bf16.f32 "
        "{%0,%1,%2,%3},{%4,%5,%6,%7},{%8,%9},{%0,%1,%2,%3};"
        : "+f"(d[0]), "+f"(d[1]), "+f"(d[2]), "+f"(d[3])
        : "r"(a[0]), "r"(a[1]), "r"(a[2]), "r"(a[3]), "r"(b0), "r"(b1));
}
#define CP16(dst, src) \
    asm volatile("cp.async.cg.shared.global [%0], [%1], 16;" :: "r"(dst), "l"(src) : "memory")
#define CP_COMMIT() asm volatile("cp.async.commit_group;" ::: "memory")
#define CP_WAIT(n)  asm volatile("cp.async.wait_group %0;" :: "n"(n) : "memory")

__device__ __forceinline__ uint32_t pack_bf16x2(float a, float b) {
    uint32_t r;
    asm("cvt.rn.bf16x2.f32 %0, %1, %2;" : "=r"(r) : "f"(b), "f"(a));  // lo=a, hi=b
    return r;
}
__device__ __forceinline__ uint32_t lo_from_pair(uint32_t hpair, float f0, float f1) {
    float fh0 = __uint_as_float(hpair << 16);
    float fh1 = __uint_as_float(hpair & 0xffff0000u);
    return pack_bf16x2(f0 - fh0, f1 - fh1);
}

// ---------------------------------------------------------------------------
// Kernel 0: split proj (D,R) fp32 -> projT hi/lo (R,D) bf16 (rn split).
// ---------------------------------------------------------------------------
__global__ __launch_bounds__(256) void prep_proj_kernel(const float* __restrict__ proj) {
    __shared__ float sT[32][33];
    const int tid = threadIdx.x;
    const int k0 = blockIdx.x * 32;
    const int r0 = blockIdx.y * 32;

#pragma unroll
    for (int t = 0; t < 2; ++t) {
        const int idx = tid + t * 256;
        const int k = idx >> 4, c2 = idx & 15;
        float2 v = *reinterpret_cast<const float2*>(proj + (size_t)(k0 + k) * RR + r0 + c2 * 2);
        sT[k][c2 * 2] = v.x;
        sT[k][c2 * 2 + 1] = v.y;
    }
    __syncthreads();

    {
        const int r = tid >> 3, kq = tid & 7;
        float f[4];
#pragma unroll
        for (int e = 0; e < 4; ++e) f[e] = sT[kq * 4 + e][r];
        uint2 hv, lv;
        hv.x = pack_bf16x2(f[0], f[1]);
        hv.y = pack_bf16x2(f[2], f[3]);
        lv.x = lo_from_pair(hv.x, f[0], f[1]);
        lv.y = lo_from_pair(hv.y, f[2], f[3]);
        const size_t o = (size_t)(r0 + r) * DD + k0 + kq * 4;
        *reinterpret_cast<uint2*>(g_pT_hi + o) = hv;
        *reinterpret_cast<uint2*>(g_pT_lo + o) = lv;
    }
}

// ---------------------------------------------------------------------------
// Kernel 1: T = batch @ proj (16384x128, K=1024), 2-term: T ~= Ah*(Bh+Bl).
// CTA 128x128, grid 128 (one wave), 256 thr, warp tile 32x64
// (wm=(wid&3)*32, wn=(wid>>2)*64), BK=64 (16 iters).
// XOR-swizzled 128B rows, double-buffered 2x48KB.
// ---------------------------------------------------------------------------
#define A1_ARR 16384                  // 128 rows x 128B
#define B1_ARR 16384
#define G1_BUF (A1_ARR + 2 * B1_ARR)  // 49152
#define G1_SMEM (2 * G1_BUF)          // 98304

__global__ __launch_bounds__(256) void gemm1_kernel(const float* __restrict__ batch) {
    extern __shared__ __align__(16) char sm1[];
    __shared__ float sSq[128][2];
    const uint32_t base = smem_u32(sm1);

    const int tid = threadIdx.x;
    const int wid = tid >> 5;
    const int lane = tid & 31;
    const int row0 = blockIdx.x * 128;
    const int wm = (wid & 3) * 32;      // M group within 128
    const int wn = (wid >> 2) * 64;     // N half within 128

    // loader maps
    const int a_row = tid >> 4, a_k4 = tid & 15;  // A: 128 rows x 16 float4, 8 per thread
    const int b_row = tid >> 3, b_c = tid & 7;    // B: 128 rows x 8 16B chunks, 4 per thread per array

    const uint32_t a_sts = (uint32_t)(a_row * 128 + (((a_k4 >> 1) ^ (a_row & 7)) << 4) + (a_k4 & 1) * 8);
    const uint32_t b_cp  = (uint32_t)(b_row * 128 + ((b_c ^ (b_row & 7)) << 4));

    // ldmatrix lane pieces (row&7 == lane&7 everywhere: offsets are multiples of 8)
    const int lx = lane & 7;
    const int a_bit = (lane >> 4) & 1;
    const int b_bit = (lane >> 3) & 1;
    const uint32_t a_rb0 = (uint32_t)((wm + (lane & 15)) * 128);        // mi=0
    const uint32_t a_rb1 = a_rb0 + 16 * 128;                            // mi=1
    const int b_lrow = (lane & 7) + ((lane >> 4) & 1) * 8;              // within 16-row group

    float acc[2][8][4];
#pragma unroll
    for (int mi = 0; mi < 2; mi++)
#pragma unroll
        for (int g = 0; g < 8; g++)
#pragma unroll
            for (int j = 0; j < 4; j++) acc[mi][g][j] = 0.0f;

    float4 pfa[8];

    // ---- prologue: iter 0 ----
#pragma unroll
    for (int t = 0; t < 8; ++t) {
        const int row = a_row + t * 16;
        pfa[t] = *reinterpret_cast<const float4*>(
            batch + (size_t)(row0 + row) * DD + a_k4 * 4);
    }
    {
        const uint32_t bb = base;
#pragma unroll
        for (int t = 0; t < 4; ++t) {
            const int row = b_row + t * 32;
            const uint32_t off = b_cp + (uint32_t)(t * 32 * 128);
            CP16(bb + A1_ARR + off, g_pT_hi + (size_t)row * DD + b_c * 8);
            CP16(bb + A1_ARR + B1_ARR + off, g_pT_lo + (size_t)row * DD + b_c * 8);
        }
        CP_COMMIT();
#pragma unroll
        for (int t = 0; t < 8; ++t) {
            float4 v = pfa[t];
            uint32_t h01 = pack_bf16x2(v.x, v.y);
            uint32_t h23 = pack_bf16x2(v.z, v.w);
            asm volatile("st.shared.v2.b32 [%0], {%1,%2};"
                :: "r"(bb + a_sts + (uint32_t)(t * 16 * 128)), "r"(h01), "r"(h23) : "memory");
        }
    }
    CP_WAIT(0);
    __syncthreads();

    for (int it = 0; it < 16; ++it) {
        const int p = it & 1;
        const uint32_t bb = base + p * G1_BUF;
        const uint32_t nb = base + (p ^ 1) * G1_BUF;

        if (it < 15) {
            const int k0n = (it + 1) * 64;
#pragma unroll
            for (int t = 0; t < 4; ++t) {
                const int row = b_row + t * 32;
                const uint32_t off = b_cp + (uint32_t)(t * 32 * 128);
                CP16(nb + A1_ARR + off, g_pT_hi + (size_t)row * DD + k0n + b_c * 8);
                CP16(nb + A1_ARR + B1_ARR + off, g_pT_lo + (size_t)row * DD + k0n + b_c * 8);
            }
            CP_COMMIT();
#pragma unroll
            for (int t = 0; t < 8; ++t) {
                const int row = a_row + t * 16;
                pfa[t] = *reinterpret_cast<const float4*>(
                    batch + (size_t)(row0 + row) * DD + k0n + a_k4 * 4);
            }
        }

        // compute on buffer p: 4 k16 steps, warp tile 32x64
#pragma unroll
        for (int s = 0; s < 4; ++s) {
            const uint32_t asw = (uint32_t)((((2 * s + a_bit) ^ lx) << 4));
            const uint32_t bsw = (uint32_t)((((2 * s + b_bit) ^ lx) << 4));
            uint32_t Ah[2][4];
            ldsm4(Ah[0], bb + a_rb0 + asw);
            ldsm4(Ah[1], bb + a_rb1 + asw);
#pragma unroll
            for (int ng = 0; ng < 4; ++ng) {
                const uint32_t brb = (uint32_t)((wn + ng * 16 + b_lrow) * 128);
                uint32_t Bh4[4], Bl4[4];
                ldsm4(Bh4, bb + A1_ARR + brb + bsw);
                ldsm4(Bl4, bb + A1_ARR + B1_ARR + brb + bsw);
#pragma unroll
                for (int mi = 0; mi < 2; ++mi) {
                    mma_bf16(acc[mi][ng * 2 + 0], Ah[mi], Bh4[0], Bh4[1]);
                    mma_bf16(acc[mi][ng * 2 + 1], Ah[mi], Bh4[2], Bh4[3]);
                    mma_bf16(acc[mi][ng * 2 + 0], Ah[mi], Bl4[0], Bl4[1]);
                    mma_bf16(acc[mi][ng * 2 + 1], Ah[mi], Bl4[2], Bl4[3]);
                }
            }
        }

        if (it < 15) {
#pragma unroll
            for (int t = 0; t < 8; ++t) {
                float4 v = pfa[t];
                uint32_t h01 = pack_bf16x2(v.x, v.y);
                uint32_t h23 = pack_bf16x2(v.z, v.w);
                asm volatile("st.shared.v2.b32 [%0], {%1,%2};"
                    :: "r"(nb + a_sts + (uint32_t)(t * 16 * 128)), "r"(h01), "r"(h23) : "memory");
            }
            CP_WAIT(0);
        }
        __syncthreads();
    }

    // Epilogue: rows wm+mi*16+(lane>>2) (+8), cols wn + g*8 + (lane&3)*2.
    uint32_t* thi32 = reinterpret_cast<uint32_t*>(g_thi);
    uint32_t* tlo32 = reinterpret_cast<uint32_t*>(g_tlo);
#pragma unroll
    for (int mi = 0; mi < 2; ++mi) {
        const int lr = wm + mi * 16 + (lane >> 2);
        const int g0 = row0 + lr, g1 = g0 + 8;
        float sq0 = 0.0f, sq1 = 0.0f;
#pragma unroll
        for (int g = 0; g < 8; ++g) {
            float f0 = acc[mi][g][0], f1 = acc[mi][g][1];
            float f2 = acc[mi][g][2], f3 = acc[mi][g][3];
            sq0 = fmaf(f0, f0, sq0); sq0 = fmaf(f1, f1, sq0);
            sq1 = fmaf(f2, f2, sq1); sq1 = fmaf(f3, f3, sq1);
            const int cidx = wn / 2 + g * 4 + (lane & 3);
            uint32_t h01 = pack_bf16x2(f0, f1);
            uint32_t h23 = pack_bf16x2(f2, f3);
            thi32[(size_t)g0 * 64 + cidx] = h01;
            thi32[(size_t)g1 * 64 + cidx] = h23;
            tlo32[(size_t)g0 * 64 + cidx] = lo_from_pair(h01, f0, f1);
            tlo32[(size_t)g1 * 64 + cidx] = lo_from_pair(h23, f2, f3);
        }
#pragma unroll
        for (int o = 1; o <= 2; o <<= 1) {
            sq0 += __shfl_xor_sync(0xffffffffu, sq0, o);
            sq1 += __shfl_xor_sync(0xffffffffu, sq1, o);
        }
        if ((lane & 3) == 0) {
            sSq[lr][wid >> 2] = sq0;
            sSq[lr + 8][wid >> 2] = sq1;
        }
    }
    __syncthreads();
    if (tid < 128) g_sqn[row0 + tid] = sSq[tid][0] + sSq[tid][1];
}

// ---------------------------------------------------------------------------
// Kernel 2: symmetric Gram tiles, 2-term: c = Thi_i * (Thj + Tlj).
// Grid (10, 32), 256 thr, warp tile 32x64 (wm 4 x wn 2), 2 CTAs/SM.
// Off-diagonal mirror via conflict-free smem transpose. Split-K cp.async.
// ---------------------------------------------------------------------------
#define S2B 272                        // bytes per smem row (136 bf16)
#define G2_TILE (128 * S2B)            // 34816
#define G2_SMEM (3 * G2_TILE + 1024)   // 105472

__global__ __launch_bounds__(256, 2) void gemm2_kernel(float* __restrict__ out) {
    extern __shared__ __align__(16) char sm2[];
    const uint32_t ah = smem_u32(sm2);
    const uint32_t bh = ah + G2_TILE;
    const uint32_t bl = ah + 2 * G2_TILE;
    float* sNi = reinterpret_cast<float*>(sm2 + 3 * G2_TILE);
    float* sNj = sNi + 128;
    float* sD  = reinterpret_cast<float*>(sm2);   // transpose staging (aliases tiles)

    const int tid = threadIdx.x;
    const int wid = tid >> 5;
    const int lane = tid & 31;
    const int b = blockIdx.y;
    const int ti = c_ti[blockIdx.x], tj = c_tj[blockIdx.x];
    const bool diag = (ti == tj);
    const int i0 = ti * 128, j0 = tj * 128;
    const int wm = (wid & 3) * 32;
    const int wn = (wid >> 2) * 64;

    const __nv_bfloat16* srcs[3] = {
        g_thi + (size_t)(b * LL + i0) * RR,   // -> ah
        g_tlo + (size_t)(b * LL + j0) * RR,   // -> bl
        g_thi + (size_t)(b * LL + j0) * RR }; // -> bh (off-diag only)
    const uint32_t dsts[3] = { ah, bl, bh };
    const int ntile = diag ? 2 : 3;

    // Split-K cp.async: group 0 = k[0,64), group 1 = k[64,128)
#pragma unroll
    for (int h = 0; h < 2; ++h) {
        for (int r = 0; r < ntile; ++r) {
#pragma unroll
            for (int q = 0; q < 4; ++q) {
                const int idx = tid + q * 256;
                const int row = idx >> 3, kcl = idx & 7;
                const int kc = h * 8 + kcl;
                CP16(dsts[r] + (uint32_t)(row * S2B + kc * 16),
                     srcs[r] + (size_t)row * RR + kc * 8);
            }
        }
        CP_COMMIT();
    }
    if (tid < 128) sNi[tid] = g_sqn[b * LL + i0 + tid];
    else sNj[tid - 128] = g_sqn[b * LL + j0 + (tid - 128)];

    const uint32_t bhc = diag ? ah : bh;
    // ldmatrix lane pieces (padded rows, no swizzle)
    const uint32_t a_off0 = (uint32_t)((wm + (lane & 15)) * S2B + ((lane >> 4) & 1) * 16);
    const uint32_t a_off1 = a_off0 + (uint32_t)(16 * S2B);
    const uint32_t b_base = (uint32_t)(((lane & 7) + ((lane >> 4) & 1) * 8) * S2B + ((lane >> 3) & 1) * 16);

    float acc[2][8][4];
#pragma unroll
    for (int mi = 0; mi < 2; mi++)
#pragma unroll
        for (int g = 0; g < 8; g++)
#pragma unroll
            for (int j = 0; j < 4; j++) acc[mi][g][j] = 0.0f;

    CP_WAIT(1);
    __syncthreads();

#pragma unroll
    for (int s = 0; s < 8; ++s) {
        if (s == 4) { CP_WAIT(0); __syncthreads(); }
        uint32_t Ah[2][4];
        ldsm4(Ah[0], ah + a_off0 + s * 32);
        ldsm4(Ah[1], ah + a_off1 + s * 32);
#pragma unroll
        for (int ng = 0; ng < 4; ++ng) {
            const uint32_t brb = b_base + (uint32_t)((wn + ng * 16) * S2B) + s * 32;
            uint32_t Bh4[4], Bl4[4];
            ldsm4(Bh4, bhc + brb);
            ldsm4(Bl4, bl + brb);
#pragma unroll
            for (int mi = 0; mi < 2; ++mi) {
                mma_bf16(acc[mi][ng * 2 + 0], Ah[mi], Bh4[0], Bh4[1]);
                mma_bf16(acc[mi][ng * 2 + 1], Ah[mi], Bh4[2], Bh4[3]);
                mma_bf16(acc[mi][ng * 2 + 0], Ah[mi], Bl4[0], Bl4[1]);
                mma_bf16(acc[mi][ng * 2 + 1], Ah[mi], Bl4[2], Bl4[3]);
            }
        }
    }
    __syncthreads();   // all ldsm done before sD overwrites tile smem

    // Epilogue: rows wm+mi*16+(lane>>2) (+8), cols wn+g*8+(lane&3)*2.
#pragma unroll
    for (int mi = 0; mi < 2; ++mi) {
        const int r = wm + mi * 16 + (lane >> 2);
        const float ni0 = sNi[r], ni1 = sNi[r + 8];
        float* o0 = out + ((size_t)(b * LL + i0 + r)) * LL + j0;
        float* o1 = o0 + 8 * LL;
#pragma unroll
        for (int g = 0; g < 8; ++g) {
            const int col = wn + g * 8 + (lane & 3) * 2;
            const float nj0 = sNj[col], nj1 = sNj[col + 1];
            float2 v0, v1;
            v0.x = fmaxf(ni0 + nj0 - 2.0f * acc[mi][g][0], 0.0f);
            v0.y = fmaxf(ni0 + nj1 - 2.0f * acc[mi][g][1], 0.0f);
            v1.x = fmaxf(ni1 + nj0 - 2.0f * acc[mi][g][2], 0.0f);
            v1.y = fmaxf(ni1 + nj1 - 2.0f * acc[mi][g][3], 0.0f);
            *reinterpret_cast<float2*>(o0 + col) = v0;
            *reinterpret_cast<float2*>(o1 + col) = v1;
            if (!diag) {
                sD[col * 132 + r]           = v0.x;   // sD_T[c][r]
                sD[(col + 1) * 132 + r]     = v0.y;
                sD[col * 132 + r + 8]       = v1.x;
                sD[(col + 1) * 132 + r + 8] = v1.y;
            }
        }
    }
    if (!diag) {
        __syncthreads();
#pragma unroll
        for (int t = 0; t < 16; ++t) {
            const int idx = tid + t * 256;
            const int tr = idx >> 5;                 // transposed row = orig col
            float4 v = *reinterpret_cast<const float4*>(sD + (size_t)tr * 132 + lane * 4);
            *reinterpret_cast<float4*>(
                out + ((size_t)(b * LL + j0 + tr)) * LL + i0 + lane * 4) = v;
        }
    }
}

extern "C" void kernel_launch(void* const* d_in, const int* in_sizes, int n_in,
                              void* d_out, int out_size)
{
    const float* batch = (const float*)d_in[0];  // (32, 512, 1024) f32
    const float* proj  = (const float*)d_in[1];  // (1024, 128) f32
    float* out = (float*)d_out;                  // (32, 512, 512) f32

    cudaFuncSetAttribute(gemm1_kernel, cudaFuncAttributeMaxDynamicSharedMemorySize, G1_SMEM);
    cudaFuncSetAttribute(gemm2_kernel, cudaFuncAttributeMaxDynamicSharedMemorySize, G2_SMEM);

    prep_proj_kernel<<<dim3(32, 4), 256>>>(proj);
    gemm1_kernel<<<M_TOTAL / 128, 256, G1_SMEM>>>(batch);
    gemm2_kernel<<<dim3(10, BB), 256, G2_SMEM>>>(out);
}

// round 16
// speedup vs baseline: 4.0384x; 1.0842x over previous
#include <cuda_runtime.h>
#include <cuda_fp16.h>
#include <cstdint>

#define BB 32
#define LL 512
#define DD 1024
#define RR 128
#define M_TOTAL (BB * LL)   // 16384

// ---------------- global scratch ----------------
__device__ __align__(16) __half g_pT_hi[RR * DD];     // projT hi [128][1024] fp16
__device__ __align__(16) __half g_pT_lo[RR * DD];     // projT lo fp16
__device__ __align__(16) __half g_th[M_TOTAL * RR];   // T-hat [16384][128] fp16
__device__ float g_sqn[M_TOTAL];                      // norms of T-hat (fp32)

__constant__ int c_ti[10] = {0,0,0,0,1,1,1,2,2,3};
__constant__ int c_tj[10] = {0,1,2,3,1,2,3,2,3,3};

// ---------------- helpers (arch-feature-free PTX only) ----------------
__device__ __forceinline__ uint32_t smem_u32(const void* p) {
    uint32_t a;
    asm("{ .reg .u64 t; cvta.to.shared.u64 t, %1; cvt.u32.u64 %0, t; }" : "=r"(a) : "l"(p));
    return a;
}
__device__ __forceinline__ void ldsm4(uint32_t r[4], uint32_t addr) {
    asm volatile("ldmatrix.sync.aligned.m8n8.x4.shared.b16 {%0,%1,%2,%3}, [%4];"
                 : "=r"(r[0]), "=r"(r[1]), "=r"(r[2]), "=r"(r[3]) : "r"(addr));
}
__device__ __forceinline__ void mma_f16(float d[4], const uint32_t a[4],
                                        uint32_t b0, uint32_t b1) {
    asm volatile(
        "mma.sync.aligned.m16n8k16.row.col.f32.f16.f16.f32 "
        "{%0,%1,%2,%3},{%4,%5,%6,%7},{%8,%9},{%0,%1,%2,%3};"
        : "+f"(d[0]), "+f"(d[1]), "+f"(d[2]), "+f"(d[3])
        : "r"(a[0]), "r"(a[1]), "r"(a[2]), "r"(a[3]), "r"(b0), "r"(b1));
}
#define CP16(dst, src) \
    asm volatile("cp.async.cg.shared.global [%0], [%1], 16;" :: "r"(dst), "l"(src) : "memory")
#define CP_COMMIT() asm volatile("cp.async.commit_group;" ::: "memory")
#define CP_WAIT(n)  asm volatile("cp.async.wait_group %0;" :: "n"(n) : "memory")

__device__ __forceinline__ uint32_t pack_f16x2(float a, float b) {
    __half2 h = __floats2half2_rn(a, b);
    return *reinterpret_cast<uint32_t*>(&h);
}
__device__ __forceinline__ float2 unpack_f16x2(uint32_t u) {
    __half2 h = *reinterpret_cast<__half2*>(&u);
    return __half22float2(h);
}

// ---------------------------------------------------------------------------
// Kernel 0: split proj (D,R) fp32 -> projT hi/lo (R,D) fp16 (rn split).
// ---------------------------------------------------------------------------
__global__ __launch_bounds__(256) void prep_proj_kernel(const float* __restrict__ proj) {
    __shared__ float sT[32][33];
    const int tid = threadIdx.x;
    const int k0 = blockIdx.x * 32;
    const int r0 = blockIdx.y * 32;

#pragma unroll
    for (int t = 0; t < 2; ++t) {
        const int idx = tid + t * 256;
        const int k = idx >> 4, c2 = idx & 15;
        float2 v = *reinterpret_cast<const float2*>(proj + (size_t)(k0 + k) * RR + r0 + c2 * 2);
        sT[k][c2 * 2] = v.x;
        sT[k][c2 * 2 + 1] = v.y;
    }
    __syncthreads();

    {
        const int r = tid >> 3, kq = tid & 7;
        float f[4];
#pragma unroll
        for (int e = 0; e < 4; ++e) f[e] = sT[kq * 4 + e][r];
        uint2 hv, lv;
        hv.x = pack_f16x2(f[0], f[1]);
        hv.y = pack_f16x2(f[2], f[3]);
        float2 h01 = unpack_f16x2(hv.x), h23 = unpack_f16x2(hv.y);
        lv.x = pack_f16x2(f[0] - h01.x, f[1] - h01.y);
        lv.y = pack_f16x2(f[2] - h23.x, f[3] - h23.y);
        const size_t o = (size_t)(r0 + r) * DD + k0 + kq * 4;
        *reinterpret_cast<uint2*>(g_pT_hi + o) = hv;
        *reinterpret_cast<uint2*>(g_pT_lo + o) = lv;
    }
}

// ---------------------------------------------------------------------------
// Kernel 1: T = batch @ proj (16384x128, K=1024), 2-term fp16: T ~= Ah*(Bh+Bl).
// CTA 128x128, grid 128, 256 thr, warp tile 32x64, BK=64 (16 iters).
// XOR-swizzled 128B rows, double-buffered 2x48KB.
// Epilogue: t-hat = fp16(acc); store t-hat; norms from t-hat (consistency
// with gemm2's single-term product => distance = |t̂i - t̂j|^2 exactly).
// ---------------------------------------------------------------------------
#define A1_ARR 16384                  // 128 rows x 128B
#define B1_ARR 16384
#define G1_BUF (A1_ARR + 2 * B1_ARR)  // 49152
#define G1_SMEM (2 * G1_BUF)          // 98304

__global__ __launch_bounds__(256) void gemm1_kernel(const float* __restrict__ batch) {
    extern __shared__ __align__(16) char sm1[];
    __shared__ float sSq[128][2];
    const uint32_t base = smem_u32(sm1);

    const int tid = threadIdx.x;
    const int wid = tid >> 5;
    const int lane = tid & 31;
    const int row0 = blockIdx.x * 128;
    const int wm = (wid & 3) * 32;      // M group within 128
    const int wn = (wid >> 2) * 64;     // N half within 128

    // loader maps
    const int a_row = tid >> 4, a_k4 = tid & 15;  // A: 128 rows x 16 float4, 8 per thread
    const int b_row = tid >> 3, b_c = tid & 7;    // B: 128 rows x 8 16B chunks

    const uint32_t a_sts = (uint32_t)(a_row * 128 + (((a_k4 >> 1) ^ (a_row & 7)) << 4) + (a_k4 & 1) * 8);
    const uint32_t b_cp  = (uint32_t)(b_row * 128 + ((b_c ^ (b_row & 7)) << 4));

    // ldmatrix lane pieces
    const int lx = lane & 7;
    const int a_bit = (lane >> 4) & 1;
    const int b_bit = (lane >> 3) & 1;
    const uint32_t a_rb0 = (uint32_t)((wm + (lane & 15)) * 128);
    const uint32_t a_rb1 = a_rb0 + 16 * 128;
    const int b_lrow = (lane & 7) + ((lane >> 4) & 1) * 8;

    float acc[2][8][4];
#pragma unroll
    for (int mi = 0; mi < 2; mi++)
#pragma unroll
        for (int g = 0; g < 8; g++)
#pragma unroll
            for (int j = 0; j < 4; j++) acc[mi][g][j] = 0.0f;

    float4 pfa[8];

    // ---- prologue: iter 0 ----
#pragma unroll
    for (int t = 0; t < 8; ++t) {
        const int row = a_row + t * 16;
        pfa[t] = *reinterpret_cast<const float4*>(
            batch + (size_t)(row0 + row) * DD + a_k4 * 4);
    }
    {
        const uint32_t bb = base;
#pragma unroll
        for (int t = 0; t < 4; ++t) {
            const int row = b_row + t * 32;
            const uint32_t off = b_cp + (uint32_t)(t * 32 * 128);
            CP16(bb + A1_ARR + off, g_pT_hi + (size_t)row * DD + b_c * 8);
            CP16(bb + A1_ARR + B1_ARR + off, g_pT_lo + (size_t)row * DD + b_c * 8);
        }
        CP_COMMIT();
#pragma unroll
        for (int t = 0; t < 8; ++t) {
            float4 v = pfa[t];
            uint32_t h01 = pack_f16x2(v.x, v.y);
            uint32_t h23 = pack_f16x2(v.z, v.w);
            asm volatile("st.shared.v2.b32 [%0], {%1,%2};"
                :: "r"(bb + a_sts + (uint32_t)(t * 16 * 128)), "r"(h01), "r"(h23) : "memory");
        }
    }
    CP_WAIT(0);
    __syncthreads();

    for (int it = 0; it < 16; ++it) {
        const int p = it & 1;
        const uint32_t bb = base + p * G1_BUF;
        const uint32_t nb = base + (p ^ 1) * G1_BUF;

        if (it < 15) {
            const int k0n = (it + 1) * 64;
#pragma unroll
            for (int t = 0; t < 4; ++t) {
                const int row = b_row + t * 32;
                const uint32_t off = b_cp + (uint32_t)(t * 32 * 128);
                CP16(nb + A1_ARR + off, g_pT_hi + (size_t)row * DD + k0n + b_c * 8);
                CP16(nb + A1_ARR + B1_ARR + off, g_pT_lo + (size_t)row * DD + k0n + b_c * 8);
            }
            CP_COMMIT();
#pragma unroll
            for (int t = 0; t < 8; ++t) {
                const int row = a_row + t * 16;
                pfa[t] = *reinterpret_cast<const float4*>(
                    batch + (size_t)(row0 + row) * DD + k0n + a_k4 * 4);
            }
        }

        // compute on buffer p: 4 k16 steps, warp tile 32x64
#pragma unroll
        for (int s = 0; s < 4; ++s) {
            const uint32_t asw = (uint32_t)((((2 * s + a_bit) ^ lx) << 4));
            const uint32_t bsw = (uint32_t)((((2 * s + b_bit) ^ lx) << 4));
            uint32_t Ah[2][4];
            ldsm4(Ah[0], bb + a_rb0 + asw);
            ldsm4(Ah[1], bb + a_rb1 + asw);
#pragma unroll
            for (int ng = 0; ng < 4; ++ng) {
                const uint32_t brb = (uint32_t)((wn + ng * 16 + b_lrow) * 128);
                uint32_t Bh4[4], Bl4[4];
                ldsm4(Bh4, bb + A1_ARR + brb + bsw);
                ldsm4(Bl4, bb + A1_ARR + B1_ARR + brb + bsw);
#pragma unroll
                for (int mi = 0; mi < 2; ++mi) {
                    mma_f16(acc[mi][ng * 2 + 0], Ah[mi], Bh4[0], Bh4[1]);
                    mma_f16(acc[mi][ng * 2 + 1], Ah[mi], Bh4[2], Bh4[3]);
                    mma_f16(acc[mi][ng * 2 + 0], Ah[mi], Bl4[0], Bl4[1]);
                    mma_f16(acc[mi][ng * 2 + 1], Ah[mi], Bl4[2], Bl4[3]);
                }
            }
        }

        if (it < 15) {
#pragma unroll
            for (int t = 0; t < 8; ++t) {
                float4 v = pfa[t];
                uint32_t h01 = pack_f16x2(v.x, v.y);
                uint32_t h23 = pack_f16x2(v.z, v.w);
                asm volatile("st.shared.v2.b32 [%0], {%1,%2};"
                    :: "r"(nb + a_sts + (uint32_t)(t * 16 * 128)), "r"(h01), "r"(h23) : "memory");
            }
            CP_WAIT(0);
        }
        __syncthreads();
    }

    // Epilogue: t-hat = fp16(acc), store; norms accumulated from ROUNDED vals.
    uint32_t* th32 = reinterpret_cast<uint32_t*>(g_th);
#pragma unroll
    for (int mi = 0; mi < 2; ++mi) {
        const int lr = wm + mi * 16 + (lane >> 2);
        const int g0 = row0 + lr, g1 = g0 + 8;
        float sq0 = 0.0f, sq1 = 0.0f;
#pragma unroll
        for (int g = 0; g < 8; ++g) {
            uint32_t h01 = pack_f16x2(acc[mi][g][0], acc[mi][g][1]);
            uint32_t h23 = pack_f16x2(acc[mi][g][2], acc[mi][g][3]);
            float2 r01 = unpack_f16x2(h01);
            float2 r23 = unpack_f16x2(h23);
            sq0 = fmaf(r01.x, r01.x, sq0); sq0 = fmaf(r01.y, r01.y, sq0);
            sq1 = fmaf(r23.x, r23.x, sq1); sq1 = fmaf(r23.y, r23.y, sq1);
            const int cidx = wn / 2 + g * 4 + (lane & 3);
            th32[(size_t)g0 * 64 + cidx] = h01;
            th32[(size_t)g1 * 64 + cidx] = h23;
        }
#pragma unroll
        for (int o = 1; o <= 2; o <<= 1) {
            sq0 += __shfl_xor_sync(0xffffffffu, sq0, o);
            sq1 += __shfl_xor_sync(0xffffffffu, sq1, o);
        }
        if ((lane & 3) == 0) {
            sSq[lr][wid >> 2] = sq0;
            sSq[lr + 8][wid >> 2] = sq1;
        }
    }
    __syncthreads();
    if (tid < 128) g_sqn[row0 + tid] = sSq[tid][0] + sSq[tid][1];
}

// ---------------------------------------------------------------------------
// Kernel 2: symmetric Gram tiles, SINGLE-term fp16: c = t̂i · t̂j.
// Grid (10, 32), 256 thr, warp tile 32x64, 2 smem tiles (A, B) -> 3 CTAs/SM
// => 320 CTAs in ONE wave (444 slots). Mirror via smem transpose.
// ---------------------------------------------------------------------------
#define S2B 272                        // bytes per smem row (136 fp16)
#define G2_TILE (128 * S2B)            // 34816
#define G2_SMEM (2 * G2_TILE + 1024)   // 70656

__global__ __launch_bounds__(256, 3) void gemm2_kernel(float* __restrict__ out) {
    extern __shared__ __align__(16) char sm2[];
    const uint32_t ah = smem_u32(sm2);
    const uint32_t bh = ah + G2_TILE;
    float* sNi = reinterpret_cast<float*>(sm2 + 2 * G2_TILE);
    float* sNj = sNi + 128;
    float* sD  = reinterpret_cast<float*>(sm2);   // transpose staging (aliases tiles)

    const int tid = threadIdx.x;
    const int wid = tid >> 5;
    const int lane = tid & 31;
    const int b = blockIdx.y;
    const int ti = c_ti[blockIdx.x], tj = c_tj[blockIdx.x];
    const bool diag = (ti == tj);
    const int i0 = ti * 128, j0 = tj * 128;
    const int wm = (wid & 3) * 32;
    const int wn = (wid >> 2) * 64;

    const __half* srcs[2] = {
        g_th + (size_t)(b * LL + i0) * RR,   // -> ah
        g_th + (size_t)(b * LL + j0) * RR }; // -> bh (off-diag only)
    const uint32_t dsts[2] = { ah, bh };
    const int ntile = diag ? 1 : 2;

    // Split-K cp.async: group 0 = k[0,64), group 1 = k[64,128)
#pragma unroll
    for (int h = 0; h < 2; ++h) {
        for (int r = 0; r < ntile; ++r) {
#pragma unroll
            for (int q = 0; q < 4; ++q) {
                const int idx = tid + q * 256;
                const int row = idx >> 3, kcl = idx & 7;
                const int kc = h * 8 + kcl;
                CP16(dsts[r] + (uint32_t)(row * S2B + kc * 16),
                     srcs[r] + (size_t)row * RR + kc * 8);
            }
        }
        CP_COMMIT();
    }
    if (tid < 128) sNi[tid] = g_sqn[b * LL + i0 + tid];
    else sNj[tid - 128] = g_sqn[b * LL + j0 + (tid - 128)];

    const uint32_t bhc = diag ? ah : bh;
    const uint32_t a_off0 = (uint32_t)((wm + (lane & 15)) * S2B + ((lane >> 4) & 1) * 16);
    const uint32_t a_off1 = a_off0 + (uint32_t)(16 * S2B);
    const uint32_t b_base = (uint32_t)(((lane & 7) + ((lane >> 4) & 1) * 8) * S2B + ((lane >> 3) & 1) * 16);

    float acc[2][8][4];
#pragma unroll
    for (int mi = 0; mi < 2; mi++)
#pragma unroll
        for (int g = 0; g < 8; g++)
#pragma unroll
            for (int j = 0; j < 4; j++) acc[mi][g][j] = 0.0f;

    CP_WAIT(1);
    __syncthreads();

#pragma unroll
    for (int s = 0; s < 8; ++s) {
        if (s == 4) { CP_WAIT(0); __syncthreads(); }
        uint32_t Ah[2][4];
        ldsm4(Ah[0], ah + a_off0 + s * 32);
        ldsm4(Ah[1], ah + a_off1 + s * 32);
#pragma unroll
        for (int ng = 0; ng < 4; ++ng) {
            const uint32_t brb = b_base + (uint32_t)((wn + ng * 16) * S2B) + s * 32;
            uint32_t Bh4[4];
            ldsm4(Bh4, bhc + brb);
#pragma unroll
            for (int mi = 0; mi < 2; ++mi) {
                mma_f16(acc[mi][ng * 2 + 0], Ah[mi], Bh4[0], Bh4[1]);
                mma_f16(acc[mi][ng * 2 + 1], Ah[mi], Bh4[2], Bh4[3]);
            }
        }
    }
    __syncthreads();   // all ldsm done before sD overwrites tile smem

    // Epilogue: d = max(ni + nj - 2c, 0); direct block + staged mirror.
#pragma unroll
    for (int mi = 0; mi < 2; ++mi) {
        const int r = wm + mi * 16 + (lane >> 2);
        const float ni0 = sNi[r], ni1 = sNi[r + 8];
        float* o0 = out + ((size_t)(b * LL + i0 + r)) * LL + j0;
        float* o1 = o0 + 8 * LL;
#pragma unroll
        for (int g = 0; g < 8; ++g) {
            const int col = wn + g * 8 + (lane & 3) * 2;
            const float nj0 = sNj[col], nj1 = sNj[col + 1];
            float2 v0, v1;
            v0.x = fmaxf(ni0 + nj0 - 2.0f * acc[mi][g][0], 0.0f);
            v0.y = fmaxf(ni0 + nj1 - 2.0f * acc[mi][g][1], 0.0f);
            v1.x = fmaxf(ni1 + nj0 - 2.0f * acc[mi][g][2], 0.0f);
            v1.y = fmaxf(ni1 + nj1 - 2.0f * acc[mi][g][3], 0.0f);
            *reinterpret_cast<float2*>(o0 + col) = v0;
            *reinterpret_cast<float2*>(o1 + col) = v1;
            if (!diag) {
                sD[col * 132 + r]           = v0.x;   // sD_T[c][r]
                sD[(col + 1) * 132 + r]     = v0.y;
                sD[col * 132 + r + 8]       = v1.x;
                sD[(col + 1) * 132 + r + 8] = v1.y;
            }
        }
    }
    if (!diag) {
        __syncthreads();
#pragma unroll
        for (int t = 0; t < 16; ++t) {
            const int idx = tid + t * 256;
            const int tr = idx >> 5;                 // transposed row = orig col
            float4 v = *reinterpret_cast<const float4*>(sD + (size_t)tr * 132 + lane * 4);
            *reinterpret_cast<float4*>(
                out + ((size_t)(b * LL + j0 + tr)) * LL + i0 + lane * 4) = v;
        }
    }
}

extern "C" void kernel_launch(void* const* d_in, const int* in_sizes, int n_in,
                              void* d_out, int out_size)
{
    const float* batch = (const float*)d_in[0];  // (32, 512, 1024) f32
    const float* proj  = (const float*)d_in[1];  // (1024, 128) f32
    float* out = (float*)d_out;                  // (32, 512, 512) f32

    cudaFuncSetAttribute(gemm1_kernel, cudaFuncAttributeMaxDynamicSharedMemorySize, G1_SMEM);
    cudaFuncSetAttribute(gemm2_kernel, cudaFuncAttributeMaxDynamicSharedMemorySize, G2_SMEM);

    prep_proj_kernel<<<dim3(32, 4), 256>>>(proj);
    gemm1_kernel<<<M_TOTAL / 128, 256, G1_SMEM>>>(batch);
    gemm2_kernel<<<dim3(10, BB), 256, G2_SMEM>>>(out);
}